// round 10
// baseline (speedup 1.0000x reference)
#include <cuda_runtime.h>
#include <stdint.h>

#define N_NODES 50000
#define D       128
#define EH      500000
#define ES      250000
#define NCLS    47
#define E_TOT   (2 * (EH + ES))

typedef unsigned long long ull;

// ---------------- scratch (device globals; no runtime allocation) ----------------
__device__ int   g_cnt[4 * N_NODES];
__device__ int   g_off[4 * (N_NODES + 1)];
__device__ int   g_cur[4 * N_NODES];
__device__ int   g_eidx[E_TOT];
__device__ float g_neigh0[N_NODES * D];   // layer-0 neigh (hist+delta)
__device__ float g_neigh1[N_NODES * D];   // layer-1 neigh (hist, then +delta)
__device__ float g_H1[N_NODES * D];       // layer-0 output
__device__ float g_Hd[N_NODES * D];       // H - HBar for current layer

__device__ __forceinline__ int eidx_base(int p) {
    return p == 0 ? 0 : p == 1 ? EH : p == 2 ? (EH + ES) : (2 * EH + ES);
}

// ---------------- f32x2 packed math helpers ----------------
__device__ __forceinline__ ull fma2(ull a, ull b, ull c) {
    ull d;
    asm("fma.rn.f32x2 %0, %1, %2, %3;" : "=l"(d) : "l"(a), "l"(b), "l"(c));
    return d;
}
__device__ __forceinline__ ull packf2(float x, float y) {
    ull d;
    asm("mov.b64 %0, {%1, %2};" : "=l"(d) : "f"(x), "f"(y));
    return d;
}
__device__ __forceinline__ void unpackf2(ull v, float& x, float& y) {
    asm("mov.b64 {%0, %1}, %2;" : "=f"(x), "=f"(y) : "l"(v));
}

// ---------------- K1: count histogram  ||  hdelta0 = x - hbar0 ----------------
#define GE_BLOCKS  ((E_TOT + 255) / 256)           // 5860
#define GEL_BLOCKS ((N_NODES * D / 4 + 255) / 256) // 6250

__global__ void count_hdelta0_kernel(const int* __restrict__ hd0, const int* __restrict__ sd0,
                                     const int* __restrict__ hd1, const int* __restrict__ sd1,
                                     const float* __restrict__ x, const float* __restrict__ hbar0) {
    int b = blockIdx.x;
    if (b < GE_BLOCKS) {
        int i = b * blockDim.x + threadIdx.x;
        if (i >= E_TOT) return;
        int pair, off;
        const int* p;
        if (i < EH)               { pair = 0; p = hd0; off = i; }
        else if (i < EH + ES)     { pair = 1; p = sd0; off = i - EH; }
        else if (i < 2 * EH + ES) { pair = 2; p = hd1; off = i - EH - ES; }
        else                      { pair = 3; p = sd1; off = i - 2 * EH - ES; }
        atomicAdd(&g_cnt[pair * N_NODES + __ldg(p + off)], 1);
    } else {
        int i = (b - GE_BLOCKS) * blockDim.x + threadIdx.x;
        if (i >= N_NODES * D / 4) return;
        float4 a = __ldg((const float4*)x + i);
        float4 h = __ldg((const float4*)hbar0 + i);
        ((float4*)g_Hd)[i] = make_float4(a.x - h.x, a.y - h.y, a.z - h.z, a.w - h.w);
    }
}

// ---------------- scan (4 blocks, one per pair) ----------------
__global__ void scan_kernel() {
    const int p = blockIdx.x;
    int* cnt = g_cnt + p * N_NODES;
    int* off = g_off + p * (N_NODES + 1);
    int* cur = g_cur + p * N_NODES;
    const int T = 1024;
    const int C = (N_NODES + T - 1) / T;
    __shared__ int part[T];
    int t = threadIdx.x;
    int base = t * C;
    int s = 0;
#pragma unroll 1
    for (int i = 0; i < C; i++) {
        int j = base + i;
        if (j < N_NODES) s += cnt[j];
    }
    part[t] = s;
    __syncthreads();
    for (int d2 = 1; d2 < T; d2 <<= 1) {
        int v = (t >= d2) ? part[t - d2] : 0;
        __syncthreads();
        part[t] += v;
        __syncthreads();
    }
    int run = part[t] - s;
#pragma unroll 1
    for (int i = 0; i < C; i++) {
        int j = base + i;
        if (j < N_NODES) {
            off[j] = run;
            cur[j] = run;
            run += cnt[j];
        }
    }
    if (t == T - 1) off[N_NODES] = part[t];
}

__global__ void bucket_all_kernel(const int* __restrict__ hs0, const int* __restrict__ hd0,
                                  const int* __restrict__ ss0, const int* __restrict__ sd0,
                                  const int* __restrict__ hs1, const int* __restrict__ hd1,
                                  const int* __restrict__ ss1, const int* __restrict__ sd1) {
    int i = blockIdx.x * blockDim.x + threadIdx.x;
    if (i >= E_TOT) return;
    int pair, off;
    const int *ps, *pd;
    if (i < EH)               { pair = 0; ps = hs0; pd = hd0; off = i; }
    else if (i < EH + ES)     { pair = 1; ps = ss0; pd = sd0; off = i - EH; }
    else if (i < 2 * EH + ES) { pair = 2; ps = hs1; pd = hd1; off = i - EH - ES; }
    else                      { pair = 3; ps = ss1; pd = sd1; off = i - 2 * EH - ES; }
    int d = __ldg(pd + off);
    int pos = atomicAdd(&g_cur[pair * N_NODES + d], 1);
    g_eidx[eidx_base(pair) + pos] = __ldg(ps + off);
}

// ---------------- gather primitives (warp-collective, MLP=4) ----------------
__device__ __forceinline__ void acc_add(float4& a, float4 v) {
    a.x += v.x; a.y += v.y; a.z += v.z; a.w += v.w;
}

__device__ __forceinline__ float4 gather_mean(const float* __restrict__ feat,
                                              const int* __restrict__ idx,
                                              int e0, int e1, int lane) {
    float4 a0 = make_float4(0,0,0,0), a1 = a0, a2 = a0, a3 = a0;
    int e = e0;
    for (; e + 4 <= e1; e += 4) {
        int i0 = __ldg(idx + e + 0), i1 = __ldg(idx + e + 1);
        int i2 = __ldg(idx + e + 2), i3 = __ldg(idx + e + 3);
        float4 v0 = __ldg((const float4*)(feat + (size_t)i0 * D) + lane);
        float4 v1 = __ldg((const float4*)(feat + (size_t)i1 * D) + lane);
        float4 v2 = __ldg((const float4*)(feat + (size_t)i2 * D) + lane);
        float4 v3 = __ldg((const float4*)(feat + (size_t)i3 * D) + lane);
        acc_add(a0, v0); acc_add(a1, v1); acc_add(a2, v2); acc_add(a3, v3);
    }
    for (; e < e1; e++) {
        int s = __ldg(idx + e);
        acc_add(a0, __ldg((const float4*)(feat + (size_t)s * D) + lane));
    }
    acc_add(a0, a1); acc_add(a2, a3); acc_add(a0, a2);
    float inv = 1.f / fmaxf((float)(e1 - e0), 1.f);
    return make_float4(a0.x * inv, a0.y * inv, a0.z * inv, a0.w * inv);
}

// ---------------- K4: agg0 (pairs 0,1 -> g_neigh0)  ||  agg1_hist (pair 2 -> g_neigh1) ----
#define GAGG_BLOCKS ((N_NODES * 32 + 255) / 256)   // 6250

__global__ void agg_combined_kernel(const float* __restrict__ hbar0,
                                    const float* __restrict__ hbar1) {
    int b = blockIdx.x;
    if (b < GAGG_BLOCKS) {
        int g = b * blockDim.x + threadIdx.x;
        int w = g >> 5, lane = g & 31;
        if (w >= N_NODES) return;
        const int* offH = g_off + 0 * (N_NODES + 1);
        const int* offD = g_off + 1 * (N_NODES + 1);
        int h0 = __ldg(offH + w), h1 = __ldg(offH + w + 1);
        int d0 = __ldg(offD + w), d1 = __ldg(offD + w + 1);
        float4 o = gather_mean(hbar0, g_eidx + eidx_base(0), h0, h1, lane);
        float4 dm = gather_mean(g_Hd,  g_eidx + eidx_base(1), d0, d1, lane);
        o.x += dm.x; o.y += dm.y; o.z += dm.z; o.w += dm.w;
        *(float4*)(g_neigh0 + (size_t)w * D + lane * 4) = o;
    } else {
        int g = (b - GAGG_BLOCKS) * blockDim.x + threadIdx.x;
        int w = g >> 5, lane = g & 31;
        if (w >= N_NODES) return;
        const int* offH = g_off + 2 * (N_NODES + 1);
        int h0 = __ldg(offH + w), h1 = __ldg(offH + w + 1);
        float4 o = gather_mean(hbar1, g_eidx + eidx_base(2), h0, h1, lane);
        *(float4*)(g_neigh1 + (size_t)w * D + lane * 4) = o;
    }
}

// ---------------- agg1_delta: g_neigh1 += mean over pair 3 of g_Hd ----------------
__global__ void agg1_delta_kernel() {
    int g = blockIdx.x * blockDim.x + threadIdx.x;
    int w = g >> 5, lane = g & 31;
    if (w >= N_NODES) return;
    const int* offD = g_off + 3 * (N_NODES + 1);
    int d0 = __ldg(offD + w), d1 = __ldg(offD + w + 1);
    if (d0 == d1) return;
    float4 dm = gather_mean(g_Hd, g_eidx + eidx_base(3), d0, d1, lane);
    float4* dst = (float4*)(g_neigh1 + (size_t)w * D + lane * 4);
    float4 o = *dst;
    o.x += dm.x; o.y += dm.y; o.z += dm.z; o.w += dm.w;
    *dst = o;
}

// ---------------- GEMM + bias + ReLU  (layer0 epilogue also writes g_Hd) ----------------
// BM=64, TM=4 for BOTH layers -> 3 CTAs/SM (6 warps/SMSP latency coverage).
template <int LAYER, int DOUT, int BM, int BN, int TM, int TN, int MAXB>
__global__ void __launch_bounds__(256, MAXB)
gemm_kernel(const float* __restrict__ Hext,
            const float* __restrict__ W,
            const float* __restrict__ bias,
            const float* __restrict__ hbar1,   // layer0 only: for fused hdelta1
            float* __restrict__ outext) {
    constexpr int BK = 32, K = 2 * D, NK = K / BK;
    constexpr int TNP = TN / 2;
    constexpr int NA = (BM * BK) / (256 * 4);
    constexpr int NB = (BN * BK) / (256 * 4);
    constexpr int APAD = BM + 4;
    constexpr int BPAD = BN + 4;

    const float* H     = (LAYER == 0) ? Hext     : g_H1;
    const float* neigh = (LAYER == 0) ? g_neigh0 : g_neigh1;
    float* out         = (LAYER == 0) ? g_H1     : outext;

    __shared__ float As[BK][APAD];
    __shared__ float Bs[BK][BPAD];

    const int t    = threadIdx.x;
    const int row0 = blockIdx.x * BM;
    const int tx   = t & 15;
    const int ty   = t >> 4;

    float4 pa[NA], pb[NB];

    auto load_tile = [&](int kit) {
        const int k0 = kit * BK;
        const float* Asrc = (k0 < D) ? (H + k0) : (neigh + (k0 - D));
#pragma unroll
        for (int v = 0; v < NA; v++) {
            int id = v * 256 + t;
            int m  = id >> 3;
            int kq = id & 7;
            int r  = min(row0 + m, N_NODES - 1);
            pa[v] = __ldg((const float4*)(Asrc + (size_t)r * D) + kq);
        }
#pragma unroll
        for (int v = 0; v < NB; v++) {
            int id = v * 256 + t;
            int n  = id >> 3;
            int kq = id & 7;
            pb[v] = (n < DOUT) ? __ldg((const float4*)(W + n * K + k0) + kq)
                               : make_float4(0.f, 0.f, 0.f, 0.f);
        }
    };
    auto store_tile = [&]() {
#pragma unroll
        for (int v = 0; v < NA; v++) {
            int id = v * 256 + t;
            int m  = id >> 3;
            int kq = id & 7;
            int col = (((m >> 2) ^ (kq >> 1)) << 2) + (m & 3);
            As[(kq << 2) + 0][col] = pa[v].x;
            As[(kq << 2) + 1][col] = pa[v].y;
            As[(kq << 2) + 2][col] = pa[v].z;
            As[(kq << 2) + 3][col] = pa[v].w;
        }
#pragma unroll
        for (int v = 0; v < NB; v++) {
            int id = v * 256 + t;
            int n  = id >> 3;
            int kq = id & 7;
            int col = (((n >> 2) ^ (kq >> 1)) << 2) + (n & 3);
            Bs[(kq << 2) + 0][col] = pb[v].x;
            Bs[(kq << 2) + 1][col] = pb[v].y;
            Bs[(kq << 2) + 2][col] = pb[v].z;
            Bs[(kq << 2) + 3][col] = pb[v].w;
        }
    };

    ull acc2[TM][TNP];
#pragma unroll
    for (int i = 0; i < TM; i++)
#pragma unroll
        for (int p = 0; p < TNP; p++) acc2[i][p] = 0ULL;

    load_tile(0);

    for (int kit = 0; kit < NK; kit++) {
        store_tile();
        __syncthreads();
        if (kit + 1 < NK) load_tile(kit + 1);

#pragma unroll
        for (int kk = 0; kk < BK; kk++) {
            const int s = (kk >> 3) & 3;
            ull ad[TM];
#pragma unroll
            for (int u = 0; u < TM / 4; u++) {
                int gA = ((TM / 4) * ty + u) ^ s;
                float4 a = *(const float4*)&As[kk][gA << 2];
                ad[4 * u + 0] = packf2(a.x, a.x);
                ad[4 * u + 1] = packf2(a.y, a.y);
                ad[4 * u + 2] = packf2(a.z, a.z);
                ad[4 * u + 3] = packf2(a.w, a.w);
            }
            ull bp[TNP];
#pragma unroll
            for (int u = 0; u < TN / 4; u++) {
                int gB = (tx * (TN / 4) + u) ^ s;
                ulonglong2 bb = *(const ulonglong2*)&Bs[kk][gB << 2];
                bp[2 * u + 0] = bb.x;
                bp[2 * u + 1] = bb.y;
            }
#pragma unroll
            for (int i = 0; i < TM; i++)
#pragma unroll
                for (int p = 0; p < TNP; p++)
                    acc2[i][p] = fma2(ad[i], bp[p], acc2[i][p]);
        }
        __syncthreads();
    }

    float bn[TN];
#pragma unroll
    for (int j = 0; j < TN; j++) {
        int n = tx * TN + j;
        bn[j] = (n < DOUT) ? __ldg(bias + n) : 0.f;
    }
#pragma unroll
    for (int i = 0; i < TM; i++) {
        int r = row0 + ty * TM + i;
        if (r >= N_NODES) continue;
        float res[TN];
#pragma unroll
        for (int p = 0; p < TNP; p++) {
            float lo, hi;
            unpackf2(acc2[i][p], lo, hi);
            res[2 * p + 0] = fmaxf(lo + bn[2 * p + 0], 0.f);
            res[2 * p + 1] = fmaxf(hi + bn[2 * p + 1], 0.f);
        }
        if (LAYER == 0) {
            // dense store + fused hdelta1: g_Hd = relu_out - hbar1
#pragma unroll
            for (int u = 0; u < TN / 4; u++) {
                int n = tx * TN + 4 * u;
                float4 o = make_float4(res[4 * u], res[4 * u + 1],
                                       res[4 * u + 2], res[4 * u + 3]);
                *(float4*)(out + (size_t)r * DOUT + n) = o;
                float4 hb = __ldg((const float4*)(hbar1 + (size_t)r * D + n));
                float4 hd = make_float4(o.x - hb.x, o.y - hb.y, o.z - hb.z, o.w - hb.w);
                *(float4*)(g_Hd + (size_t)r * D + n) = hd;
            }
        } else {
#pragma unroll
            for (int j = 0; j < TN; j++) {
                int n = tx * TN + j;
                if (n < DOUT) out[(size_t)r * DOUT + n] = res[j];
            }
        }
    }
}

// ---------------- launch ----------------
extern "C" void kernel_launch(void* const* d_in, const int* in_sizes, int n_in,
                              void* d_out, int out_size) {
    const float* x     = (const float*)d_in[0];
    const float* hbar0 = (const float*)d_in[1];
    const float* hbar1 = (const float*)d_in[2];
    const float* W0    = (const float*)d_in[3];
    const float* b0    = (const float*)d_in[4];
    const float* W1    = (const float*)d_in[5];
    const float* b1    = (const float*)d_in[6];
    const int* hsrc0   = (const int*)d_in[7];
    const int* hdst0   = (const int*)d_in[8];
    const int* ssrc0   = (const int*)d_in[9];
    const int* sdst0   = (const int*)d_in[10];
    const int* hsrc1   = (const int*)d_in[11];
    const int* hdst1   = (const int*)d_in[12];
    const int* ssrc1   = (const int*)d_in[13];
    const int* sdst1   = (const int*)d_in[14];
    float* out = (float*)d_out;

    // ---- K0: zero counters ----
    void* cnt_ptr = nullptr;
    cudaGetSymbolAddress(&cnt_ptr, g_cnt);
    cudaMemsetAsync(cnt_ptr, 0, sizeof(int) * 4 * N_NODES);

    // ---- K1: count || hdelta0 ----
    count_hdelta0_kernel<<<GE_BLOCKS + GEL_BLOCKS, 256>>>(hdst0, sdst0, hdst1, sdst1, x, hbar0);

    // ---- K2/K3: scan + bucket ----
    scan_kernel<<<4, 1024>>>();
    bucket_all_kernel<<<GE_BLOCKS, 256>>>(hsrc0, hdst0, ssrc0, sdst0,
                                          hsrc1, hdst1, ssrc1, sdst1);

    // ---- K4: agg0 || agg1_hist ----
    agg_combined_kernel<<<2 * GAGG_BLOCKS, 256>>>(hbar0, hbar1);

    // ---- K5: gemm0 (+ fused hdelta1 epilogue), BM=64 @ 3 CTAs/SM ----
    gemm_kernel<0, 128, 64, 128, 4, 8, 3><<<(N_NODES + 63) / 64, 256>>>(x, W0, b0, hbar1, nullptr);

    // ---- K6: agg1_delta ----
    agg1_delta_kernel<<<GAGG_BLOCKS, 256>>>();

    // ---- K7: gemm1 ----
    gemm_kernel<1, NCLS, 64, 64, 4, 4, 3><<<(N_NODES + 63) / 64, 256>>>(nullptr, W1, b1, nullptr, out);
}

// round 11
// speedup vs baseline: 1.1534x; 1.1534x over previous
#include <cuda_runtime.h>
#include <stdint.h>

#define N_NODES 50000
#define D       128
#define EH      500000
#define ES      250000
#define NCLS    47
#define E_TOT   (2 * (EH + ES))

typedef unsigned long long ull;

// ---------------- scratch (device globals; no runtime allocation) ----------------
__device__ int   g_cnt[4 * N_NODES];
__device__ int   g_off[4 * (N_NODES + 1)];
__device__ int   g_cur[4 * N_NODES];
__device__ int   g_eidx[E_TOT];
__device__ float g_neigh0[N_NODES * D];
__device__ float g_neigh1[N_NODES * D];
__device__ float g_H1[N_NODES * D];
__device__ float g_Hd[N_NODES * D];

__device__ __forceinline__ int eidx_base(int p) {
    return p == 0 ? 0 : p == 1 ? EH : p == 2 ? (EH + ES) : (2 * EH + ES);
}

// ---------------- f32x2 packed math helpers ----------------
__device__ __forceinline__ ull fma2(ull a, ull b, ull c) {
    ull d;
    asm("fma.rn.f32x2 %0, %1, %2, %3;" : "=l"(d) : "l"(a), "l"(b), "l"(c));
    return d;
}
__device__ __forceinline__ ull packf2(float x, float y) {
    ull d;
    asm("mov.b64 %0, {%1, %2};" : "=l"(d) : "f"(x), "f"(y));
    return d;
}
__device__ __forceinline__ void unpackf2(ull v, float& x, float& y) {
    asm("mov.b64 {%0, %1}, %2;" : "=f"(x), "=f"(y) : "l"(v));
}

// ---------------- K1: count histogram  ||  hdelta0 = x - hbar0 ----------------
#define GE_BLOCKS  ((E_TOT + 255) / 256)           // 5860
#define GEL_BLOCKS ((N_NODES * D / 4 + 255) / 256) // 6250

__global__ void count_hdelta0_kernel(const int* __restrict__ hd0, const int* __restrict__ sd0,
                                     const int* __restrict__ hd1, const int* __restrict__ sd1,
                                     const float* __restrict__ x, const float* __restrict__ hbar0) {
    int b = blockIdx.x;
    if (b < GE_BLOCKS) {
        int i = b * blockDim.x + threadIdx.x;
        if (i >= E_TOT) return;
        int pair, off;
        const int* p;
        if (i < EH)               { pair = 0; p = hd0; off = i; }
        else if (i < EH + ES)     { pair = 1; p = sd0; off = i - EH; }
        else if (i < 2 * EH + ES) { pair = 2; p = hd1; off = i - EH - ES; }
        else                      { pair = 3; p = sd1; off = i - 2 * EH - ES; }
        atomicAdd(&g_cnt[pair * N_NODES + __ldg(p + off)], 1);
    } else {
        int i = (b - GE_BLOCKS) * blockDim.x + threadIdx.x;
        if (i >= N_NODES * D / 4) return;
        float4 a = __ldg((const float4*)x + i);
        float4 h = __ldg((const float4*)hbar0 + i);
        ((float4*)g_Hd)[i] = make_float4(a.x - h.x, a.y - h.y, a.z - h.z, a.w - h.w);
    }
}

// ---------------- scan (4 blocks, one per pair) ----------------
__global__ void scan_kernel() {
    const int p = blockIdx.x;
    int* cnt = g_cnt + p * N_NODES;
    int* off = g_off + p * (N_NODES + 1);
    int* cur = g_cur + p * N_NODES;
    const int T = 1024;
    const int C = (N_NODES + T - 1) / T;
    __shared__ int part[T];
    int t = threadIdx.x;
    int base = t * C;
    int s = 0;
#pragma unroll 1
    for (int i = 0; i < C; i++) {
        int j = base + i;
        if (j < N_NODES) s += cnt[j];
    }
    part[t] = s;
    __syncthreads();
    for (int d2 = 1; d2 < T; d2 <<= 1) {
        int v = (t >= d2) ? part[t - d2] : 0;
        __syncthreads();
        part[t] += v;
        __syncthreads();
    }
    int run = part[t] - s;
#pragma unroll 1
    for (int i = 0; i < C; i++) {
        int j = base + i;
        if (j < N_NODES) {
            off[j] = run;
            cur[j] = run;
            run += cnt[j];
        }
    }
    if (t == T - 1) off[N_NODES] = part[t];
}

__global__ void bucket_all_kernel(const int* __restrict__ hs0, const int* __restrict__ hd0,
                                  const int* __restrict__ ss0, const int* __restrict__ sd0,
                                  const int* __restrict__ hs1, const int* __restrict__ hd1,
                                  const int* __restrict__ ss1, const int* __restrict__ sd1) {
    int i = blockIdx.x * blockDim.x + threadIdx.x;
    if (i >= E_TOT) return;
    int pair, off;
    const int *ps, *pd;
    if (i < EH)               { pair = 0; ps = hs0; pd = hd0; off = i; }
    else if (i < EH + ES)     { pair = 1; ps = ss0; pd = sd0; off = i - EH; }
    else if (i < 2 * EH + ES) { pair = 2; ps = hs1; pd = hd1; off = i - EH - ES; }
    else                      { pair = 3; ps = ss1; pd = sd1; off = i - 2 * EH - ES; }
    int d = __ldg(pd + off);
    int pos = atomicAdd(&g_cur[pair * N_NODES + d], 1);
    g_eidx[eidx_base(pair) + pos] = __ldg(ps + off);
}

// ---------------- gather primitives (warp-collective, MLP=4) ----------------
__device__ __forceinline__ void acc_add(float4& a, float4 v) {
    a.x += v.x; a.y += v.y; a.z += v.z; a.w += v.w;
}

__device__ __forceinline__ float4 gather_mean(const float* __restrict__ feat,
                                              const int* __restrict__ idx,
                                              int e0, int e1, int lane) {
    float4 a0 = make_float4(0,0,0,0), a1 = a0, a2 = a0, a3 = a0;
    int e = e0;
    for (; e + 4 <= e1; e += 4) {
        int i0 = __ldg(idx + e + 0), i1 = __ldg(idx + e + 1);
        int i2 = __ldg(idx + e + 2), i3 = __ldg(idx + e + 3);
        float4 v0 = __ldg((const float4*)(feat + (size_t)i0 * D) + lane);
        float4 v1 = __ldg((const float4*)(feat + (size_t)i1 * D) + lane);
        float4 v2 = __ldg((const float4*)(feat + (size_t)i2 * D) + lane);
        float4 v3 = __ldg((const float4*)(feat + (size_t)i3 * D) + lane);
        acc_add(a0, v0); acc_add(a1, v1); acc_add(a2, v2); acc_add(a3, v3);
    }
    for (; e < e1; e++) {
        int s = __ldg(idx + e);
        acc_add(a0, __ldg((const float4*)(feat + (size_t)s * D) + lane));
    }
    acc_add(a0, a1); acc_add(a2, a3); acc_add(a0, a2);
    float inv = 1.f / fmaxf((float)(e1 - e0), 1.f);
    return make_float4(a0.x * inv, a0.y * inv, a0.z * inv, a0.w * inv);
}

// ---------------- K4: agg0 (pairs 0,1 -> g_neigh0)  ||  agg1_hist (pair 2 -> g_neigh1) ----
#define GAGG_BLOCKS ((N_NODES * 32 + 255) / 256)   // 6250

__global__ void agg_combined_kernel(const float* __restrict__ hbar0,
                                    const float* __restrict__ hbar1) {
    int b = blockIdx.x;
    if (b < GAGG_BLOCKS) {
        int g = b * blockDim.x + threadIdx.x;
        int w = g >> 5, lane = g & 31;
        if (w >= N_NODES) return;
        const int* offH = g_off + 0 * (N_NODES + 1);
        const int* offD = g_off + 1 * (N_NODES + 1);
        int h0 = __ldg(offH + w), h1 = __ldg(offH + w + 1);
        int d0 = __ldg(offD + w), d1 = __ldg(offD + w + 1);
        float4 o = gather_mean(hbar0, g_eidx + eidx_base(0), h0, h1, lane);
        float4 dm = gather_mean(g_Hd,  g_eidx + eidx_base(1), d0, d1, lane);
        o.x += dm.x; o.y += dm.y; o.z += dm.z; o.w += dm.w;
        *(float4*)(g_neigh0 + (size_t)w * D + lane * 4) = o;
    } else {
        int g = (b - GAGG_BLOCKS) * blockDim.x + threadIdx.x;
        int w = g >> 5, lane = g & 31;
        if (w >= N_NODES) return;
        const int* offH = g_off + 2 * (N_NODES + 1);
        int h0 = __ldg(offH + w), h1 = __ldg(offH + w + 1);
        float4 o = gather_mean(hbar1, g_eidx + eidx_base(2), h0, h1, lane);
        *(float4*)(g_neigh1 + (size_t)w * D + lane * 4) = o;
    }
}

// ---------------- agg1_delta: g_neigh1 += mean over pair 3 of g_Hd ----------------
__global__ void agg1_delta_kernel() {
    int g = blockIdx.x * blockDim.x + threadIdx.x;
    int w = g >> 5, lane = g & 31;
    if (w >= N_NODES) return;
    const int* offD = g_off + 3 * (N_NODES + 1);
    int d0 = __ldg(offD + w), d1 = __ldg(offD + w + 1);
    if (d0 == d1) return;
    float4 dm = gather_mean(g_Hd, g_eidx + eidx_base(3), d0, d1, lane);
    float4* dst = (float4*)(g_neigh1 + (size_t)w * D + lane * 4);
    float4 o = *dst;
    o.x += dm.x; o.y += dm.y; o.z += dm.z; o.w += dm.w;
    *dst = o;
}

// ---------------- GEMM + bias + ReLU  (layer0 epilogue also writes g_Hd) ----------------
// NTILES: N-dimension split. blockIdx.x = tile * NTILES + nt; col offset = nt*BN.
template <int LAYER, int DOUT, int BM, int BN, int TM, int TN, int NTILES, int MAXB>
__global__ void __launch_bounds__(256, MAXB)
gemm_kernel(const float* __restrict__ Hext,
            const float* __restrict__ W,
            const float* __restrict__ bias,
            const float* __restrict__ hbar1,   // layer0 only: for fused hdelta1
            float* __restrict__ outext) {
    constexpr int BK = 32, K = 2 * D, NK = K / BK;
    constexpr int TNP = TN / 2;
    constexpr int NA = (BM * BK) / (256 * 4);
    constexpr int NB = (BN * BK) / (256 * 4);
    constexpr int APAD = BM + 4;
    constexpr int BPAD = BN + 4;

    const float* H     = (LAYER == 0) ? Hext     : g_H1;
    const float* neigh = (LAYER == 0) ? g_neigh0 : g_neigh1;
    float* out         = (LAYER == 0) ? g_H1     : outext;

    __shared__ float As[BK][APAD];
    __shared__ float Bs[BK][BPAD];

    const int t    = threadIdx.x;
    const int tile = (NTILES == 1) ? blockIdx.x : (blockIdx.x / NTILES);
    const int nb0  = (NTILES == 1) ? 0 : (blockIdx.x % NTILES) * BN;
    const int row0 = tile * BM;
    const int tx   = t & 15;
    const int ty   = t >> 4;

    float4 pa[NA], pb[NB];

    auto load_tile = [&](int kit) {
        const int k0 = kit * BK;
        const float* Asrc = (k0 < D) ? (H + k0) : (neigh + (k0 - D));
#pragma unroll
        for (int v = 0; v < NA; v++) {
            int id = v * 256 + t;
            int m  = id >> 3;
            int kq = id & 7;
            int r  = min(row0 + m, N_NODES - 1);
            pa[v] = __ldg((const float4*)(Asrc + (size_t)r * D) + kq);
        }
#pragma unroll
        for (int v = 0; v < NB; v++) {
            int id = v * 256 + t;
            int n  = nb0 + (id >> 3);
            int kq = id & 7;
            pb[v] = (n < DOUT) ? __ldg((const float4*)(W + (size_t)n * K + k0) + kq)
                               : make_float4(0.f, 0.f, 0.f, 0.f);
        }
    };
    auto store_tile = [&]() {
#pragma unroll
        for (int v = 0; v < NA; v++) {
            int id = v * 256 + t;
            int m  = id >> 3;
            int kq = id & 7;
            int col = (((m >> 2) ^ (kq >> 1)) << 2) + (m & 3);
            As[(kq << 2) + 0][col] = pa[v].x;
            As[(kq << 2) + 1][col] = pa[v].y;
            As[(kq << 2) + 2][col] = pa[v].z;
            As[(kq << 2) + 3][col] = pa[v].w;
        }
#pragma unroll
        for (int v = 0; v < NB; v++) {
            int id = v * 256 + t;
            int n  = id >> 3;
            int kq = id & 7;
            int col = (((n >> 2) ^ (kq >> 1)) << 2) + (n & 3);
            Bs[(kq << 2) + 0][col] = pb[v].x;
            Bs[(kq << 2) + 1][col] = pb[v].y;
            Bs[(kq << 2) + 2][col] = pb[v].z;
            Bs[(kq << 2) + 3][col] = pb[v].w;
        }
    };

    ull acc2[TM][TNP];
#pragma unroll
    for (int i = 0; i < TM; i++)
#pragma unroll
        for (int p = 0; p < TNP; p++) acc2[i][p] = 0ULL;

    load_tile(0);

    for (int kit = 0; kit < NK; kit++) {
        store_tile();
        __syncthreads();
        if (kit + 1 < NK) load_tile(kit + 1);

#pragma unroll
        for (int kk = 0; kk < BK; kk++) {
            const int s = (kk >> 3) & 3;
            ull ad[TM];
#pragma unroll
            for (int u = 0; u < TM / 4; u++) {
                int gA = ((TM / 4) * ty + u) ^ s;
                float4 a = *(const float4*)&As[kk][gA << 2];
                ad[4 * u + 0] = packf2(a.x, a.x);
                ad[4 * u + 1] = packf2(a.y, a.y);
                ad[4 * u + 2] = packf2(a.z, a.z);
                ad[4 * u + 3] = packf2(a.w, a.w);
            }
            ull bp[TNP];
#pragma unroll
            for (int u = 0; u < TN / 4; u++) {
                int gB = (tx * (TN / 4) + u) ^ s;
                ulonglong2 bb = *(const ulonglong2*)&Bs[kk][gB << 2];
                bp[2 * u + 0] = bb.x;
                bp[2 * u + 1] = bb.y;
            }
#pragma unroll
            for (int i = 0; i < TM; i++)
#pragma unroll
                for (int p = 0; p < TNP; p++)
                    acc2[i][p] = fma2(ad[i], bp[p], acc2[i][p]);
        }
        __syncthreads();
    }

    float bn[TN];
#pragma unroll
    for (int j = 0; j < TN; j++) {
        int n = nb0 + tx * TN + j;
        bn[j] = (n < DOUT) ? __ldg(bias + n) : 0.f;
    }
#pragma unroll
    for (int i = 0; i < TM; i++) {
        int r = row0 + ty * TM + i;
        if (r >= N_NODES) continue;
        float res[TN];
#pragma unroll
        for (int p = 0; p < TNP; p++) {
            float lo, hi;
            unpackf2(acc2[i][p], lo, hi);
            res[2 * p + 0] = fmaxf(lo + bn[2 * p + 0], 0.f);
            res[2 * p + 1] = fmaxf(hi + bn[2 * p + 1], 0.f);
        }
        if (LAYER == 0) {
            // dense store + fused hdelta1: g_Hd = relu_out - hbar1
#pragma unroll
            for (int u = 0; u < TN / 4; u++) {
                int n = nb0 + tx * TN + 4 * u;
                float4 o = make_float4(res[4 * u], res[4 * u + 1],
                                       res[4 * u + 2], res[4 * u + 3]);
                *(float4*)(out + (size_t)r * DOUT + n) = o;
                float4 hb = __ldg((const float4*)(hbar1 + (size_t)r * D + n));
                float4 hd = make_float4(o.x - hb.x, o.y - hb.y, o.z - hb.z, o.w - hb.w);
                *(float4*)(g_Hd + (size_t)r * D + n) = hd;
            }
        } else {
#pragma unroll
            for (int j = 0; j < TN; j++) {
                int n = nb0 + tx * TN + j;
                if (n < DOUT) out[(size_t)r * DOUT + n] = res[j];
            }
        }
    }
}

// ---------------- launch ----------------
extern "C" void kernel_launch(void* const* d_in, const int* in_sizes, int n_in,
                              void* d_out, int out_size) {
    const float* x     = (const float*)d_in[0];
    const float* hbar0 = (const float*)d_in[1];
    const float* hbar1 = (const float*)d_in[2];
    const float* W0    = (const float*)d_in[3];
    const float* b0    = (const float*)d_in[4];
    const float* W1    = (const float*)d_in[5];
    const float* b1    = (const float*)d_in[6];
    const int* hsrc0   = (const int*)d_in[7];
    const int* hdst0   = (const int*)d_in[8];
    const int* ssrc0   = (const int*)d_in[9];
    const int* sdst0   = (const int*)d_in[10];
    const int* hsrc1   = (const int*)d_in[11];
    const int* hdst1   = (const int*)d_in[12];
    const int* ssrc1   = (const int*)d_in[13];
    const int* sdst1   = (const int*)d_in[14];
    float* out = (float*)d_out;

    // ---- K0: zero counters ----
    void* cnt_ptr = nullptr;
    cudaGetSymbolAddress(&cnt_ptr, g_cnt);
    cudaMemsetAsync(cnt_ptr, 0, sizeof(int) * 4 * N_NODES);

    // ---- K1: count || hdelta0 ----
    count_hdelta0_kernel<<<GE_BLOCKS + GEL_BLOCKS, 256>>>(hdst0, sdst0, hdst1, sdst1, x, hbar0);

    // ---- K2/K3: scan + bucket ----
    scan_kernel<<<4, 1024>>>();
    bucket_all_kernel<<<GE_BLOCKS, 256>>>(hsrc0, hdst0, ssrc0, sdst0,
                                          hsrc1, hdst1, ssrc1, sdst1);

    // ---- K4: agg0 || agg1_hist ----
    agg_combined_kernel<<<2 * GAGG_BLOCKS, 256>>>(hbar0, hbar1);

    // ---- K5: gemm0, BM=128 x BN=64, N split in 2 (grid 782), fused hdelta1 ----
    gemm_kernel<0, 128, 128, 64, 8, 4, 2, 2>
        <<<((N_NODES + 127) / 128) * 2, 256>>>(x, W0, b0, hbar1, nullptr);

    // ---- K6: agg1_delta ----
    agg1_delta_kernel<<<GAGG_BLOCKS, 256>>>();

    // ---- K7: gemm1 (unchanged from R9) ----
    gemm_kernel<1, NCLS, 64, 64, 4, 4, 1, 3>
        <<<(N_NODES + 63) / 64, 256>>>(nullptr, W1, b1, nullptr, out);
}

// round 12
// speedup vs baseline: 1.1626x; 1.0080x over previous
#include <cuda_runtime.h>
#include <stdint.h>

#define N_NODES 50000
#define D       128
#define EH      500000
#define ES      250000
#define NCLS    47
#define E_TOT   (2 * (EH + ES))

typedef unsigned long long ull;

// ---------------- scratch (device globals; no runtime allocation) ----------------
__device__ int   g_cnt[4 * N_NODES];
__device__ int   g_off[4 * (N_NODES + 1)];
__device__ int   g_cur[4 * N_NODES];
__device__ int   g_eidx[E_TOT];
__device__ float g_neigh0[N_NODES * D];
__device__ float g_neigh1[N_NODES * D];
__device__ float g_H1[N_NODES * D];
__device__ float g_Hd[N_NODES * D];

__device__ __forceinline__ int eidx_base(int p) {
    return p == 0 ? 0 : p == 1 ? EH : p == 2 ? (EH + ES) : (2 * EH + ES);
}

// ---------------- f32x2 packed math helpers ----------------
__device__ __forceinline__ ull fma2(ull a, ull b, ull c) {
    ull d;
    asm("fma.rn.f32x2 %0, %1, %2, %3;" : "=l"(d) : "l"(a), "l"(b), "l"(c));
    return d;
}
__device__ __forceinline__ ull packf2(float x, float y) {
    ull d;
    asm("mov.b64 %0, {%1, %2};" : "=l"(d) : "f"(x), "f"(y));
    return d;
}
__device__ __forceinline__ void unpackf2(ull v, float& x, float& y) {
    asm("mov.b64 {%0, %1}, %2;" : "=f"(x), "=f"(y) : "l"(v));
}

// ---------------- K1: count histogram  ||  hdelta0 = x - hbar0 ----------------
#define GE_BLOCKS  ((E_TOT + 255) / 256)           // 5860
#define GEL_BLOCKS ((N_NODES * D / 4 + 255) / 256) // 6250

__global__ void count_hdelta0_kernel(const int* __restrict__ hd0, const int* __restrict__ sd0,
                                     const int* __restrict__ hd1, const int* __restrict__ sd1,
                                     const float* __restrict__ x, const float* __restrict__ hbar0) {
    int b = blockIdx.x;
    if (b < GE_BLOCKS) {
        int i = b * blockDim.x + threadIdx.x;
        if (i >= E_TOT) return;
        int pair, off;
        const int* p;
        if (i < EH)               { pair = 0; p = hd0; off = i; }
        else if (i < EH + ES)     { pair = 1; p = sd0; off = i - EH; }
        else if (i < 2 * EH + ES) { pair = 2; p = hd1; off = i - EH - ES; }
        else                      { pair = 3; p = sd1; off = i - 2 * EH - ES; }
        atomicAdd(&g_cnt[pair * N_NODES + __ldg(p + off)], 1);
    } else {
        int i = (b - GE_BLOCKS) * blockDim.x + threadIdx.x;
        if (i >= N_NODES * D / 4) return;
        float4 a = __ldg((const float4*)x + i);
        float4 h = __ldg((const float4*)hbar0 + i);
        ((float4*)g_Hd)[i] = make_float4(a.x - h.x, a.y - h.y, a.z - h.z, a.w - h.w);
    }
}

// ---------------- scan (4 blocks, one per pair) ----------------
__global__ void scan_kernel() {
    const int p = blockIdx.x;
    int* cnt = g_cnt + p * N_NODES;
    int* off = g_off + p * (N_NODES + 1);
    int* cur = g_cur + p * N_NODES;
    const int T = 1024;
    const int C = (N_NODES + T - 1) / T;
    __shared__ int part[T];
    int t = threadIdx.x;
    int base = t * C;
    int s = 0;
#pragma unroll 1
    for (int i = 0; i < C; i++) {
        int j = base + i;
        if (j < N_NODES) s += cnt[j];
    }
    part[t] = s;
    __syncthreads();
    for (int d2 = 1; d2 < T; d2 <<= 1) {
        int v = (t >= d2) ? part[t - d2] : 0;
        __syncthreads();
        part[t] += v;
        __syncthreads();
    }
    int run = part[t] - s;
#pragma unroll 1
    for (int i = 0; i < C; i++) {
        int j = base + i;
        if (j < N_NODES) {
            off[j] = run;
            cur[j] = run;
            run += cnt[j];
        }
    }
    if (t == T - 1) off[N_NODES] = part[t];
}

__global__ void bucket_all_kernel(const int* __restrict__ hs0, const int* __restrict__ hd0,
                                  const int* __restrict__ ss0, const int* __restrict__ sd0,
                                  const int* __restrict__ hs1, const int* __restrict__ hd1,
                                  const int* __restrict__ ss1, const int* __restrict__ sd1) {
    int i = blockIdx.x * blockDim.x + threadIdx.x;
    if (i >= E_TOT) return;
    int pair, off;
    const int *ps, *pd;
    if (i < EH)               { pair = 0; ps = hs0; pd = hd0; off = i; }
    else if (i < EH + ES)     { pair = 1; ps = ss0; pd = sd0; off = i - EH; }
    else if (i < 2 * EH + ES) { pair = 2; ps = hs1; pd = hd1; off = i - EH - ES; }
    else                      { pair = 3; ps = ss1; pd = sd1; off = i - 2 * EH - ES; }
    int d = __ldg(pd + off);
    int pos = atomicAdd(&g_cur[pair * N_NODES + d], 1);
    g_eidx[eidx_base(pair) + pos] = __ldg(ps + off);
}

// ---------------- gather primitives (warp-collective, MLP=4) ----------------
__device__ __forceinline__ void acc_add(float4& a, float4 v) {
    a.x += v.x; a.y += v.y; a.z += v.z; a.w += v.w;
}

__device__ __forceinline__ float4 gather_mean(const float* __restrict__ feat,
                                              const int* __restrict__ idx,
                                              int e0, int e1, int lane) {
    float4 a0 = make_float4(0,0,0,0), a1 = a0, a2 = a0, a3 = a0;
    int e = e0;
    for (; e + 4 <= e1; e += 4) {
        int i0 = __ldg(idx + e + 0), i1 = __ldg(idx + e + 1);
        int i2 = __ldg(idx + e + 2), i3 = __ldg(idx + e + 3);
        float4 v0 = __ldg((const float4*)(feat + (size_t)i0 * D) + lane);
        float4 v1 = __ldg((const float4*)(feat + (size_t)i1 * D) + lane);
        float4 v2 = __ldg((const float4*)(feat + (size_t)i2 * D) + lane);
        float4 v3 = __ldg((const float4*)(feat + (size_t)i3 * D) + lane);
        acc_add(a0, v0); acc_add(a1, v1); acc_add(a2, v2); acc_add(a3, v3);
    }
    for (; e < e1; e++) {
        int s = __ldg(idx + e);
        acc_add(a0, __ldg((const float4*)(feat + (size_t)s * D) + lane));
    }
    acc_add(a0, a1); acc_add(a2, a3); acc_add(a0, a2);
    float inv = 1.f / fmaxf((float)(e1 - e0), 1.f);
    return make_float4(a0.x * inv, a0.y * inv, a0.z * inv, a0.w * inv);
}

// ---------------- K4: agg0 (pairs 0,1 -> g_neigh0)  ||  agg1_hist (pair 2 -> g_neigh1) ----
#define GAGG_BLOCKS ((N_NODES * 32 + 255) / 256)   // 6250

__global__ void agg_combined_kernel(const float* __restrict__ hbar0,
                                    const float* __restrict__ hbar1) {
    int b = blockIdx.x;
    if (b < GAGG_BLOCKS) {
        int g = b * blockDim.x + threadIdx.x;
        int w = g >> 5, lane = g & 31;
        if (w >= N_NODES) return;
        const int* offH = g_off + 0 * (N_NODES + 1);
        const int* offD = g_off + 1 * (N_NODES + 1);
        int h0 = __ldg(offH + w), h1 = __ldg(offH + w + 1);
        int d0 = __ldg(offD + w), d1 = __ldg(offD + w + 1);
        float4 o = gather_mean(hbar0, g_eidx + eidx_base(0), h0, h1, lane);
        float4 dm = gather_mean(g_Hd,  g_eidx + eidx_base(1), d0, d1, lane);
        o.x += dm.x; o.y += dm.y; o.z += dm.z; o.w += dm.w;
        *(float4*)(g_neigh0 + (size_t)w * D + lane * 4) = o;
    } else {
        int g = (b - GAGG_BLOCKS) * blockDim.x + threadIdx.x;
        int w = g >> 5, lane = g & 31;
        if (w >= N_NODES) return;
        const int* offH = g_off + 2 * (N_NODES + 1);
        int h0 = __ldg(offH + w), h1 = __ldg(offH + w + 1);
        float4 o = gather_mean(hbar1, g_eidx + eidx_base(2), h0, h1, lane);
        *(float4*)(g_neigh1 + (size_t)w * D + lane * 4) = o;
    }
}

// ---------------- agg1_delta: g_neigh1 += mean over pair 3 of g_Hd ----------------
__global__ void agg1_delta_kernel() {
    int g = blockIdx.x * blockDim.x + threadIdx.x;
    int w = g >> 5, lane = g & 31;
    if (w >= N_NODES) return;
    const int* offD = g_off + 3 * (N_NODES + 1);
    int d0 = __ldg(offD + w), d1 = __ldg(offD + w + 1);
    if (d0 == d1) return;
    float4 dm = gather_mean(g_Hd, g_eidx + eidx_base(3), d0, d1, lane);
    float4* dst = (float4*)(g_neigh1 + (size_t)w * D + lane * 4);
    float4 o = *dst;
    o.x += dm.x; o.y += dm.y; o.z += dm.z; o.w += dm.w;
    *dst = o;
}

// ---------------- GEMM + bias + ReLU, double-buffered smem (1 sync / k-iter) ----
// NTILES: N-dimension split. blockIdx.x = tile * NTILES + nt; col offset = nt*BN.
// Dynamic smem: As[2][BK][APAD] then Bs[2][BK][BPAD].
template <int LAYER, int DOUT, int BM, int BN, int TM, int TN, int NTILES, int MAXB>
__global__ void __launch_bounds__(256, MAXB)
gemm_kernel(const float* __restrict__ Hext,
            const float* __restrict__ W,
            const float* __restrict__ bias,
            const float* __restrict__ hbar1,   // layer0 only: for fused hdelta1
            float* __restrict__ outext) {
    constexpr int BK = 32, K = 2 * D, NK = K / BK;
    constexpr int TNP = TN / 2;
    constexpr int NA = (BM * BK) / (256 * 4);
    constexpr int NB = (BN * BK) / (256 * 4);
    constexpr int APAD = BM + 4;
    constexpr int BPAD = BN + 4;
    constexpr int ASTRIDE = BK * APAD;   // floats per A buffer
    constexpr int BSTRIDE = BK * BPAD;

    const float* H     = (LAYER == 0) ? Hext     : g_H1;
    const float* neigh = (LAYER == 0) ? g_neigh0 : g_neigh1;
    float* out         = (LAYER == 0) ? g_H1     : outext;

    extern __shared__ float smem[];
    float* AsBase = smem;                    // [2][BK][APAD]
    float* BsBase = smem + 2 * ASTRIDE;      // [2][BK][BPAD]

    const int t    = threadIdx.x;
    const int tile = (NTILES == 1) ? blockIdx.x : (blockIdx.x / NTILES);
    const int nb0  = (NTILES == 1) ? 0 : (blockIdx.x % NTILES) * BN;
    const int row0 = tile * BM;
    const int tx   = t & 15;
    const int ty   = t >> 4;

    float4 pa[NA], pb[NB];

    auto load_tile = [&](int kit) {
        const int k0 = kit * BK;
        const float* Asrc = (k0 < D) ? (H + k0) : (neigh + (k0 - D));
#pragma unroll
        for (int v = 0; v < NA; v++) {
            int id = v * 256 + t;
            int m  = id >> 3;
            int kq = id & 7;
            int r  = min(row0 + m, N_NODES - 1);
            pa[v] = __ldg((const float4*)(Asrc + (size_t)r * D) + kq);
        }
#pragma unroll
        for (int v = 0; v < NB; v++) {
            int id = v * 256 + t;
            int n  = nb0 + (id >> 3);
            int kq = id & 7;
            pb[v] = (n < DOUT) ? __ldg((const float4*)(W + (size_t)n * K + k0) + kq)
                               : make_float4(0.f, 0.f, 0.f, 0.f);
        }
    };
    auto store_tile = [&](int buf) {
        float* As = AsBase + buf * ASTRIDE;
        float* Bs = BsBase + buf * BSTRIDE;
#pragma unroll
        for (int v = 0; v < NA; v++) {
            int id = v * 256 + t;
            int m  = id >> 3;
            int kq = id & 7;
            int col = (((m >> 2) ^ (kq >> 1)) << 2) + (m & 3);
            As[((kq << 2) + 0) * APAD + col] = pa[v].x;
            As[((kq << 2) + 1) * APAD + col] = pa[v].y;
            As[((kq << 2) + 2) * APAD + col] = pa[v].z;
            As[((kq << 2) + 3) * APAD + col] = pa[v].w;
        }
#pragma unroll
        for (int v = 0; v < NB; v++) {
            int id = v * 256 + t;
            int n  = id >> 3;
            int kq = id & 7;
            int col = (((n >> 2) ^ (kq >> 1)) << 2) + (n & 3);
            Bs[((kq << 2) + 0) * BPAD + col] = pb[v].x;
            Bs[((kq << 2) + 1) * BPAD + col] = pb[v].y;
            Bs[((kq << 2) + 2) * BPAD + col] = pb[v].z;
            Bs[((kq << 2) + 3) * BPAD + col] = pb[v].w;
        }
    };

    ull acc2[TM][TNP];
#pragma unroll
    for (int i = 0; i < TM; i++)
#pragma unroll
        for (int p = 0; p < TNP; p++) acc2[i][p] = 0ULL;

    // ---- pipeline preamble ----
    load_tile(0);
    store_tile(0);
    load_tile(1);          // NK >= 2 always
    __syncthreads();

    for (int kit = 0; kit < NK; kit++) {
        // store tile kit+1 (regs loaded last iteration) into the other buffer.
        // That buffer was last READ at compute(kit-1), protected by prev sync.
        if (kit + 1 < NK) store_tile((kit + 1) & 1);
        if (kit + 2 < NK) load_tile(kit + 2);

        const float* As = AsBase + (kit & 1) * ASTRIDE;
        const float* Bs = BsBase + (kit & 1) * BSTRIDE;
#pragma unroll
        for (int kk = 0; kk < BK; kk++) {
            const int s = (kk >> 3) & 3;
            ull ad[TM];
#pragma unroll
            for (int u = 0; u < TM / 4; u++) {
                int gA = ((TM / 4) * ty + u) ^ s;
                float4 a = *(const float4*)&As[kk * APAD + (gA << 2)];
                ad[4 * u + 0] = packf2(a.x, a.x);
                ad[4 * u + 1] = packf2(a.y, a.y);
                ad[4 * u + 2] = packf2(a.z, a.z);
                ad[4 * u + 3] = packf2(a.w, a.w);
            }
            ull bp[TNP];
#pragma unroll
            for (int u = 0; u < TN / 4; u++) {
                int gB = (tx * (TN / 4) + u) ^ s;
                ulonglong2 bb = *(const ulonglong2*)&Bs[kk * BPAD + (gB << 2)];
                bp[2 * u + 0] = bb.x;
                bp[2 * u + 1] = bb.y;
            }
#pragma unroll
            for (int i = 0; i < TM; i++)
#pragma unroll
                for (int p = 0; p < TNP; p++)
                    acc2[i][p] = fma2(ad[i], bp[p], acc2[i][p]);
        }
        __syncthreads();
    }

    float bn[TN];
#pragma unroll
    for (int j = 0; j < TN; j++) {
        int n = nb0 + tx * TN + j;
        bn[j] = (n < DOUT) ? __ldg(bias + n) : 0.f;
    }
#pragma unroll
    for (int i = 0; i < TM; i++) {
        int r = row0 + ty * TM + i;
        if (r >= N_NODES) continue;
        float res[TN];
#pragma unroll
        for (int p = 0; p < TNP; p++) {
            float lo, hi;
            unpackf2(acc2[i][p], lo, hi);
            res[2 * p + 0] = fmaxf(lo + bn[2 * p + 0], 0.f);
            res[2 * p + 1] = fmaxf(hi + bn[2 * p + 1], 0.f);
        }
        if (LAYER == 0) {
            // dense store + fused hdelta1: g_Hd = relu_out - hbar1
#pragma unroll
            for (int u = 0; u < TN / 4; u++) {
                int n = nb0 + tx * TN + 4 * u;
                float4 o = make_float4(res[4 * u], res[4 * u + 1],
                                       res[4 * u + 2], res[4 * u + 3]);
                *(float4*)(out + (size_t)r * DOUT + n) = o;
                float4 hb = __ldg((const float4*)(hbar1 + (size_t)r * D + n));
                float4 hd = make_float4(o.x - hb.x, o.y - hb.y, o.z - hb.z, o.w - hb.w);
                *(float4*)(g_Hd + (size_t)r * D + n) = hd;
            }
        } else {
#pragma unroll
            for (int j = 0; j < TN; j++) {
                int n = nb0 + tx * TN + j;
                if (n < DOUT) out[(size_t)r * DOUT + n] = res[j];
            }
        }
    }
}

// ---------------- launch ----------------
extern "C" void kernel_launch(void* const* d_in, const int* in_sizes, int n_in,
                              void* d_out, int out_size) {
    const float* x     = (const float*)d_in[0];
    const float* hbar0 = (const float*)d_in[1];
    const float* hbar1 = (const float*)d_in[2];
    const float* W0    = (const float*)d_in[3];
    const float* b0    = (const float*)d_in[4];
    const float* W1    = (const float*)d_in[5];
    const float* b1    = (const float*)d_in[6];
    const int* hsrc0   = (const int*)d_in[7];
    const int* hdst0   = (const int*)d_in[8];
    const int* ssrc0   = (const int*)d_in[9];
    const int* sdst0   = (const int*)d_in[10];
    const int* hsrc1   = (const int*)d_in[11];
    const int* hdst1   = (const int*)d_in[12];
    const int* ssrc1   = (const int*)d_in[13];
    const int* sdst1   = (const int*)d_in[14];
    float* out = (float*)d_out;

    // dynamic smem sizes: 2 * BK * (BM+4 + BN+4) floats
    const int SM0 = 2 * 32 * ((128 + 4) + (64 + 4)) * 4;  // 51200 B
    const int SM1 = 2 * 32 * ((64 + 4) + (64 + 4)) * 4;   // 34816 B
    cudaFuncSetAttribute((const void*)gemm_kernel<0, 128, 128, 64, 8, 4, 2, 2>,
                         cudaFuncAttributeMaxDynamicSharedMemorySize, SM0);
    cudaFuncSetAttribute((const void*)gemm_kernel<1, NCLS, 64, 64, 4, 4, 1, 3>,
                         cudaFuncAttributeMaxDynamicSharedMemorySize, SM1);

    // ---- K0: zero counters ----
    void* cnt_ptr = nullptr;
    cudaGetSymbolAddress(&cnt_ptr, g_cnt);
    cudaMemsetAsync(cnt_ptr, 0, sizeof(int) * 4 * N_NODES);

    // ---- K1: count || hdelta0 ----
    count_hdelta0_kernel<<<GE_BLOCKS + GEL_BLOCKS, 256>>>(hdst0, sdst0, hdst1, sdst1, x, hbar0);

    // ---- K2/K3: scan + bucket ----
    scan_kernel<<<4, 1024>>>();
    bucket_all_kernel<<<GE_BLOCKS, 256>>>(hsrc0, hdst0, ssrc0, sdst0,
                                          hsrc1, hdst1, ssrc1, sdst1);

    // ---- K4: agg0 || agg1_hist ----
    agg_combined_kernel<<<2 * GAGG_BLOCKS, 256>>>(hbar0, hbar1);

    // ---- K5: gemm0, BM=128 x BN=64, N split in 2 (grid 782), fused hdelta1 ----
    gemm_kernel<0, 128, 128, 64, 8, 4, 2, 2>
        <<<((N_NODES + 127) / 128) * 2, 256, SM0>>>(x, W0, b0, hbar1, nullptr);

    // ---- K6: agg1_delta ----
    agg1_delta_kernel<<<GAGG_BLOCKS, 256>>>();

    // ---- K7: gemm1 ----
    gemm_kernel<1, NCLS, 64, 64, 4, 4, 1, 3>
        <<<(N_NODES + 63) / 64, 256, SM1>>>(nullptr, W1, b1, nullptr, out);
}

// round 13
// speedup vs baseline: 1.1748x; 1.0105x over previous
#include <cuda_runtime.h>
#include <cuda_fp16.h>
#include <stdint.h>

#define N_NODES 50000
#define D       128
#define EH      500000
#define ES      250000
#define NCLS    47
#define E_TOT   (2 * (EH + ES))

typedef unsigned long long ull;

// ---------------- scratch (device globals; no runtime allocation) ----------------
__device__ int    g_cnt[4 * N_NODES];
__device__ int    g_off[4 * (N_NODES + 1)];
__device__ int    g_cur[4 * N_NODES];
__device__ int    g_eidx[E_TOT];
__device__ float  g_neigh0[N_NODES * D];
__device__ float  g_neigh1[N_NODES * D];
__device__ float  g_H1[N_NODES * D];
__device__ __half g_hb0h[N_NODES * D];    // fp16 copy of hbar0
__device__ __half g_hb1h[N_NODES * D];    // fp16 copy of hbar1
__device__ __half g_Hd16[N_NODES * D];    // fp16 (H - HBar) for current layer

__device__ __forceinline__ int eidx_base(int p) {
    return p == 0 ? 0 : p == 1 ? EH : p == 2 ? (EH + ES) : (2 * EH + ES);
}

// ---------------- f32x2 packed math helpers ----------------
__device__ __forceinline__ ull fma2(ull a, ull b, ull c) {
    ull d;
    asm("fma.rn.f32x2 %0, %1, %2, %3;" : "=l"(d) : "l"(a), "l"(b), "l"(c));
    return d;
}
__device__ __forceinline__ ull packf2(float x, float y) {
    ull d;
    asm("mov.b64 %0, {%1, %2};" : "=l"(d) : "f"(x), "f"(y));
    return d;
}
__device__ __forceinline__ void unpackf2(ull v, float& x, float& y) {
    asm("mov.b64 {%0, %1}, %2;" : "=f"(x), "=f"(y) : "l"(v));
}

// ---------------- fp16 pack helpers ----------------
__device__ __forceinline__ uint2 pack_h4(float a, float b, float c, float d) {
    __half2 p0 = __floats2half2_rn(a, b);
    __half2 p1 = __floats2half2_rn(c, d);
    uint2 u;
    u.x = *(uint32_t*)&p0;
    u.y = *(uint32_t*)&p1;
    return u;
}

// ---------------- K1: count || (hdelta0 + cvt hbar0) || cvt hbar1 ----------------
#define GE_BLOCKS  ((E_TOT + 255) / 256)           // 5860
#define GEL_BLOCKS ((N_NODES * D / 4 + 255) / 256) // 6250

__global__ void count_cvt_kernel(const int* __restrict__ hd0, const int* __restrict__ sd0,
                                 const int* __restrict__ hd1, const int* __restrict__ sd1,
                                 const float* __restrict__ x, const float* __restrict__ hbar0,
                                 const float* __restrict__ hbar1) {
    int b = blockIdx.x;
    if (b < GE_BLOCKS) {
        int i = b * blockDim.x + threadIdx.x;
        if (i >= E_TOT) return;
        int pair, off;
        const int* p;
        if (i < EH)               { pair = 0; p = hd0; off = i; }
        else if (i < EH + ES)     { pair = 1; p = sd0; off = i - EH; }
        else if (i < 2 * EH + ES) { pair = 2; p = hd1; off = i - EH - ES; }
        else                      { pair = 3; p = sd1; off = i - 2 * EH - ES; }
        atomicAdd(&g_cnt[pair * N_NODES + __ldg(p + off)], 1);
    } else if (b < GE_BLOCKS + GEL_BLOCKS) {
        // g_Hd16 = half(x - hbar0);  g_hb0h = half(hbar0)
        int i = (b - GE_BLOCKS) * blockDim.x + threadIdx.x;
        if (i >= N_NODES * D / 4) return;
        float4 a = __ldg((const float4*)x + i);
        float4 h = __ldg((const float4*)hbar0 + i);
        ((uint2*)g_Hd16)[i] = pack_h4(a.x - h.x, a.y - h.y, a.z - h.z, a.w - h.w);
        ((uint2*)g_hb0h)[i] = pack_h4(h.x, h.y, h.z, h.w);
    } else {
        // g_hb1h = half(hbar1)
        int i = (b - GE_BLOCKS - GEL_BLOCKS) * blockDim.x + threadIdx.x;
        if (i >= N_NODES * D / 4) return;
        float4 h = __ldg((const float4*)hbar1 + i);
        ((uint2*)g_hb1h)[i] = pack_h4(h.x, h.y, h.z, h.w);
    }
}

// ---------------- scan (4 blocks, one per pair) ----------------
__global__ void scan_kernel() {
    const int p = blockIdx.x;
    int* cnt = g_cnt + p * N_NODES;
    int* off = g_off + p * (N_NODES + 1);
    int* cur = g_cur + p * N_NODES;
    const int T = 1024;
    const int C = (N_NODES + T - 1) / T;
    __shared__ int part[T];
    int t = threadIdx.x;
    int base = t * C;
    int s = 0;
#pragma unroll 1
    for (int i = 0; i < C; i++) {
        int j = base + i;
        if (j < N_NODES) s += cnt[j];
    }
    part[t] = s;
    __syncthreads();
    for (int d2 = 1; d2 < T; d2 <<= 1) {
        int v = (t >= d2) ? part[t - d2] : 0;
        __syncthreads();
        part[t] += v;
        __syncthreads();
    }
    int run = part[t] - s;
#pragma unroll 1
    for (int i = 0; i < C; i++) {
        int j = base + i;
        if (j < N_NODES) {
            off[j] = run;
            cur[j] = run;
            run += cnt[j];
        }
    }
    if (t == T - 1) off[N_NODES] = part[t];
}

__global__ void bucket_all_kernel(const int* __restrict__ hs0, const int* __restrict__ hd0,
                                  const int* __restrict__ ss0, const int* __restrict__ sd0,
                                  const int* __restrict__ hs1, const int* __restrict__ hd1,
                                  const int* __restrict__ ss1, const int* __restrict__ sd1) {
    int i = blockIdx.x * blockDim.x + threadIdx.x;
    if (i >= E_TOT) return;
    int pair, off;
    const int *ps, *pd;
    if (i < EH)               { pair = 0; ps = hs0; pd = hd0; off = i; }
    else if (i < EH + ES)     { pair = 1; ps = ss0; pd = sd0; off = i - EH; }
    else if (i < 2 * EH + ES) { pair = 2; ps = hs1; pd = hd1; off = i - EH - ES; }
    else                      { pair = 3; ps = ss1; pd = sd1; off = i - 2 * EH - ES; }
    int d = __ldg(pd + off);
    int pos = atomicAdd(&g_cur[pair * N_NODES + d], 1);
    g_eidx[eidx_base(pair) + pos] = __ldg(ps + off);
}

// ---------------- fp16 gather primitives (warp-collective, MLP=4) ----------------
__device__ __forceinline__ void acc_add16(float4& a, uint2 u) {
    __half2 h0 = *(__half2*)&u.x;
    __half2 h1 = *(__half2*)&u.y;
    float2 f0 = __half22float2(h0);
    float2 f1 = __half22float2(h1);
    a.x += f0.x; a.y += f0.y; a.z += f1.x; a.w += f1.y;
}
__device__ __forceinline__ void acc_add(float4& a, float4 v) {
    a.x += v.x; a.y += v.y; a.z += v.z; a.w += v.w;
}

__device__ __forceinline__ float4 gather_mean16(const __half* __restrict__ feat,
                                                const int* __restrict__ idx,
                                                int e0, int e1, int lane) {
    float4 a0 = make_float4(0,0,0,0), a1 = a0, a2 = a0, a3 = a0;
    int e = e0;
    for (; e + 4 <= e1; e += 4) {
        int i0 = __ldg(idx + e + 0), i1 = __ldg(idx + e + 1);
        int i2 = __ldg(idx + e + 2), i3 = __ldg(idx + e + 3);
        uint2 u0 = __ldg((const uint2*)(feat + (size_t)i0 * D) + lane);
        uint2 u1 = __ldg((const uint2*)(feat + (size_t)i1 * D) + lane);
        uint2 u2 = __ldg((const uint2*)(feat + (size_t)i2 * D) + lane);
        uint2 u3 = __ldg((const uint2*)(feat + (size_t)i3 * D) + lane);
        acc_add16(a0, u0); acc_add16(a1, u1); acc_add16(a2, u2); acc_add16(a3, u3);
    }
    for (; e < e1; e++) {
        int s = __ldg(idx + e);
        acc_add16(a0, __ldg((const uint2*)(feat + (size_t)s * D) + lane));
    }
    acc_add(a0, a1); acc_add(a2, a3); acc_add(a0, a2);
    float inv = 1.f / fmaxf((float)(e1 - e0), 1.f);
    return make_float4(a0.x * inv, a0.y * inv, a0.z * inv, a0.w * inv);
}

// ---------------- K4: agg0 (pairs 0,1 -> g_neigh0)  ||  agg1_hist (pair 2 -> g_neigh1) ----
#define GAGG_BLOCKS ((N_NODES * 32 + 255) / 256)   // 6250

__global__ void agg_combined_kernel() {
    int b = blockIdx.x;
    if (b < GAGG_BLOCKS) {
        int g = b * blockDim.x + threadIdx.x;
        int w = g >> 5, lane = g & 31;
        if (w >= N_NODES) return;
        const int* offH = g_off + 0 * (N_NODES + 1);
        const int* offD = g_off + 1 * (N_NODES + 1);
        int h0 = __ldg(offH + w), h1 = __ldg(offH + w + 1);
        int d0 = __ldg(offD + w), d1 = __ldg(offD + w + 1);
        float4 o  = gather_mean16(g_hb0h, g_eidx + eidx_base(0), h0, h1, lane);
        float4 dm = gather_mean16(g_Hd16, g_eidx + eidx_base(1), d0, d1, lane);
        o.x += dm.x; o.y += dm.y; o.z += dm.z; o.w += dm.w;
        *(float4*)(g_neigh0 + (size_t)w * D + lane * 4) = o;
    } else {
        int g = (b - GAGG_BLOCKS) * blockDim.x + threadIdx.x;
        int w = g >> 5, lane = g & 31;
        if (w >= N_NODES) return;
        const int* offH = g_off + 2 * (N_NODES + 1);
        int h0 = __ldg(offH + w), h1 = __ldg(offH + w + 1);
        float4 o = gather_mean16(g_hb1h, g_eidx + eidx_base(2), h0, h1, lane);
        *(float4*)(g_neigh1 + (size_t)w * D + lane * 4) = o;
    }
}

// ---------------- agg1_delta: g_neigh1 += mean over pair 3 of g_Hd16 ----------------
__global__ void agg1_delta_kernel() {
    int g = blockIdx.x * blockDim.x + threadIdx.x;
    int w = g >> 5, lane = g & 31;
    if (w >= N_NODES) return;
    const int* offD = g_off + 3 * (N_NODES + 1);
    int d0 = __ldg(offD + w), d1 = __ldg(offD + w + 1);
    if (d0 == d1) return;
    float4 dm = gather_mean16(g_Hd16, g_eidx + eidx_base(3), d0, d1, lane);
    float4* dst = (float4*)(g_neigh1 + (size_t)w * D + lane * 4);
    float4 o = *dst;
    o.x += dm.x; o.y += dm.y; o.z += dm.z; o.w += dm.w;
    *dst = o;
}

// ---------------- GEMM + bias + ReLU, double-buffered smem (1 sync / k-iter) ----
template <int LAYER, int DOUT, int BM, int BN, int TM, int TN, int NTILES, int MAXB>
__global__ void __launch_bounds__(256, MAXB)
gemm_kernel(const float* __restrict__ Hext,
            const float* __restrict__ W,
            const float* __restrict__ bias,
            const float* __restrict__ hbar1,   // layer0 only: for fused hdelta1
            float* __restrict__ outext) {
    constexpr int BK = 32, K = 2 * D, NK = K / BK;
    constexpr int TNP = TN / 2;
    constexpr int NA = (BM * BK) / (256 * 4);
    constexpr int NB = (BN * BK) / (256 * 4);
    constexpr int APAD = BM + 4;
    constexpr int BPAD = BN + 4;
    constexpr int ASTRIDE = BK * APAD;
    constexpr int BSTRIDE = BK * BPAD;

    const float* H     = (LAYER == 0) ? Hext     : g_H1;
    const float* neigh = (LAYER == 0) ? g_neigh0 : g_neigh1;
    float* out         = (LAYER == 0) ? g_H1     : outext;

    extern __shared__ float smem[];
    float* AsBase = smem;
    float* BsBase = smem + 2 * ASTRIDE;

    const int t    = threadIdx.x;
    const int tile = (NTILES == 1) ? blockIdx.x : (blockIdx.x / NTILES);
    const int nb0  = (NTILES == 1) ? 0 : (blockIdx.x % NTILES) * BN;
    const int row0 = tile * BM;
    const int tx   = t & 15;
    const int ty   = t >> 4;

    float4 pa[NA], pb[NB];

    auto load_tile = [&](int kit) {
        const int k0 = kit * BK;
        const float* Asrc = (k0 < D) ? (H + k0) : (neigh + (k0 - D));
#pragma unroll
        for (int v = 0; v < NA; v++) {
            int id = v * 256 + t;
            int m  = id >> 3;
            int kq = id & 7;
            int r  = min(row0 + m, N_NODES - 1);
            pa[v] = __ldg((const float4*)(Asrc + (size_t)r * D) + kq);
        }
#pragma unroll
        for (int v = 0; v < NB; v++) {
            int id = v * 256 + t;
            int n  = nb0 + (id >> 3);
            int kq = id & 7;
            pb[v] = (n < DOUT) ? __ldg((const float4*)(W + (size_t)n * K + k0) + kq)
                               : make_float4(0.f, 0.f, 0.f, 0.f);
        }
    };
    auto store_tile = [&](int buf) {
        float* As = AsBase + buf * ASTRIDE;
        float* Bs = BsBase + buf * BSTRIDE;
#pragma unroll
        for (int v = 0; v < NA; v++) {
            int id = v * 256 + t;
            int m  = id >> 3;
            int kq = id & 7;
            int col = (((m >> 2) ^ (kq >> 1)) << 2) + (m & 3);
            As[((kq << 2) + 0) * APAD + col] = pa[v].x;
            As[((kq << 2) + 1) * APAD + col] = pa[v].y;
            As[((kq << 2) + 2) * APAD + col] = pa[v].z;
            As[((kq << 2) + 3) * APAD + col] = pa[v].w;
        }
#pragma unroll
        for (int v = 0; v < NB; v++) {
            int id = v * 256 + t;
            int n  = id >> 3;
            int kq = id & 7;
            int col = (((n >> 2) ^ (kq >> 1)) << 2) + (n & 3);
            Bs[((kq << 2) + 0) * BPAD + col] = pb[v].x;
            Bs[((kq << 2) + 1) * BPAD + col] = pb[v].y;
            Bs[((kq << 2) + 2) * BPAD + col] = pb[v].z;
            Bs[((kq << 2) + 3) * BPAD + col] = pb[v].w;
        }
    };

    ull acc2[TM][TNP];
#pragma unroll
    for (int i = 0; i < TM; i++)
#pragma unroll
        for (int p = 0; p < TNP; p++) acc2[i][p] = 0ULL;

    load_tile(0);
    store_tile(0);
    load_tile(1);
    __syncthreads();

    for (int kit = 0; kit < NK; kit++) {
        if (kit + 1 < NK) store_tile((kit + 1) & 1);
        if (kit + 2 < NK) load_tile(kit + 2);

        const float* As = AsBase + (kit & 1) * ASTRIDE;
        const float* Bs = BsBase + (kit & 1) * BSTRIDE;
#pragma unroll
        for (int kk = 0; kk < BK; kk++) {
            const int s = (kk >> 3) & 3;
            ull ad[TM];
#pragma unroll
            for (int u = 0; u < TM / 4; u++) {
                int gA = ((TM / 4) * ty + u) ^ s;
                float4 a = *(const float4*)&As[kk * APAD + (gA << 2)];
                ad[4 * u + 0] = packf2(a.x, a.x);
                ad[4 * u + 1] = packf2(a.y, a.y);
                ad[4 * u + 2] = packf2(a.z, a.z);
                ad[4 * u + 3] = packf2(a.w, a.w);
            }
            ull bp[TNP];
#pragma unroll
            for (int u = 0; u < TN / 4; u++) {
                int gB = (tx * (TN / 4) + u) ^ s;
                ulonglong2 bb = *(const ulonglong2*)&Bs[kk * BPAD + (gB << 2)];
                bp[2 * u + 0] = bb.x;
                bp[2 * u + 1] = bb.y;
            }
#pragma unroll
            for (int i = 0; i < TM; i++)
#pragma unroll
                for (int p = 0; p < TNP; p++)
                    acc2[i][p] = fma2(ad[i], bp[p], acc2[i][p]);
        }
        __syncthreads();
    }

    float bn[TN];
#pragma unroll
    for (int j = 0; j < TN; j++) {
        int n = nb0 + tx * TN + j;
        bn[j] = (n < DOUT) ? __ldg(bias + n) : 0.f;
    }
#pragma unroll
    for (int i = 0; i < TM; i++) {
        int r = row0 + ty * TM + i;
        if (r >= N_NODES) continue;
        float res[TN];
#pragma unroll
        for (int p = 0; p < TNP; p++) {
            float lo, hi;
            unpackf2(acc2[i][p], lo, hi);
            res[2 * p + 0] = fmaxf(lo + bn[2 * p + 0], 0.f);
            res[2 * p + 1] = fmaxf(hi + bn[2 * p + 1], 0.f);
        }
        if (LAYER == 0) {
            // dense store + fused hdelta1: g_Hd16 = half(relu_out - hbar1)
#pragma unroll
            for (int u = 0; u < TN / 4; u++) {
                int n = nb0 + tx * TN + 4 * u;
                float4 o = make_float4(res[4 * u], res[4 * u + 1],
                                       res[4 * u + 2], res[4 * u + 3]);
                *(float4*)(out + (size_t)r * DOUT + n) = o;
                float4 hb = __ldg((const float4*)(hbar1 + (size_t)r * D + n));
                *(uint2*)(g_Hd16 + (size_t)r * D + n) =
                    pack_h4(o.x - hb.x, o.y - hb.y, o.z - hb.z, o.w - hb.w);
            }
        } else {
#pragma unroll
            for (int j = 0; j < TN; j++) {
                int n = nb0 + tx * TN + j;
                if (n < DOUT) out[(size_t)r * DOUT + n] = res[j];
            }
        }
    }
}

// ---------------- launch ----------------
extern "C" void kernel_launch(void* const* d_in, const int* in_sizes, int n_in,
                              void* d_out, int out_size) {
    const float* x     = (const float*)d_in[0];
    const float* hbar0 = (const float*)d_in[1];
    const float* hbar1 = (const float*)d_in[2];
    const float* W0    = (const float*)d_in[3];
    const float* b0    = (const float*)d_in[4];
    const float* W1    = (const float*)d_in[5];
    const float* b1    = (const float*)d_in[6];
    const int* hsrc0   = (const int*)d_in[7];
    const int* hdst0   = (const int*)d_in[8];
    const int* ssrc0   = (const int*)d_in[9];
    const int* sdst0   = (const int*)d_in[10];
    const int* hsrc1   = (const int*)d_in[11];
    const int* hdst1   = (const int*)d_in[12];
    const int* ssrc1   = (const int*)d_in[13];
    const int* sdst1   = (const int*)d_in[14];
    float* out = (float*)d_out;

    // dynamic smem sizes: 2 * BK * (BM+4 + BN+4) floats
    const int SM0 = 2 * 32 * ((128 + 4) + (64 + 4)) * 4;  // 51200 B
    const int SM1 = 2 * 32 * ((64 + 4) + (64 + 4)) * 4;   // 34816 B
    cudaFuncSetAttribute((const void*)gemm_kernel<0, 128, 128, 64, 8, 4, 2, 2>,
                         cudaFuncAttributeMaxDynamicSharedMemorySize, SM0);
    cudaFuncSetAttribute((const void*)gemm_kernel<1, NCLS, 64, 64, 4, 4, 1, 3>,
                         cudaFuncAttributeMaxDynamicSharedMemorySize, SM1);

    // ---- K0: zero counters ----
    void* cnt_ptr = nullptr;
    cudaGetSymbolAddress(&cnt_ptr, g_cnt);
    cudaMemsetAsync(cnt_ptr, 0, sizeof(int) * 4 * N_NODES);

    // ---- K1: count || (hdelta0+cvt hbar0) || cvt hbar1 ----
    count_cvt_kernel<<<GE_BLOCKS + 2 * GEL_BLOCKS, 256>>>(hdst0, sdst0, hdst1, sdst1,
                                                          x, hbar0, hbar1);

    // ---- K2/K3: scan + bucket ----
    scan_kernel<<<4, 1024>>>();
    bucket_all_kernel<<<GE_BLOCKS, 256>>>(hsrc0, hdst0, ssrc0, sdst0,
                                          hsrc1, hdst1, ssrc1, sdst1);

    // ---- K4: agg0 || agg1_hist (fp16 gathers) ----
    agg_combined_kernel<<<2 * GAGG_BLOCKS, 256>>>();

    // ---- K5: gemm0, BM=128 x BN=64, N split in 2, fused fp16 hdelta1 ----
    gemm_kernel<0, 128, 128, 64, 8, 4, 2, 2>
        <<<((N_NODES + 127) / 128) * 2, 256, SM0>>>(x, W0, b0, hbar1, nullptr);

    // ---- K6: agg1_delta (fp16 gather) ----
    agg1_delta_kernel<<<GAGG_BLOCKS, 256>>>();

    // ---- K7: gemm1 ----
    gemm_kernel<1, NCLS, 64, 64, 4, 4, 1, 3>
        <<<(N_NODES + 63) / 64, 256, SM1>>>(nullptr, W1, b1, nullptr, out);
}

// round 14
// speedup vs baseline: 1.4981x; 1.2752x over previous
#include <cuda_runtime.h>
#include <cuda_fp16.h>
#include <stdint.h>

#define N_NODES 50000
#define D       128
#define EH      500000
#define ES      250000
#define NCLS    47
#define E_TOT   (2 * (EH + ES))

typedef unsigned long long ull;

// ---------------- scratch (device globals; no runtime allocation) ----------------
__device__ int    g_cnt[4 * N_NODES];
__device__ int    g_off[4 * (N_NODES + 1)];
__device__ int    g_cur[4 * N_NODES];
__device__ int    g_eidx[E_TOT];
__device__ float  g_neigh0[N_NODES * D];
__device__ float  g_neigh1[N_NODES * D];
__device__ float  g_H1[N_NODES * D];
__device__ __half g_hb0h[N_NODES * D];    // fp16 copy of hbar0
__device__ __half g_hb1h[N_NODES * D];    // fp16 copy of hbar1
__device__ __half g_Hd16[N_NODES * D];    // fp16 (H - HBar) for current layer

__device__ __forceinline__ int eidx_base(int p) {
    return p == 0 ? 0 : p == 1 ? EH : p == 2 ? (EH + ES) : (2 * EH + ES);
}

// ---------------- fp16 pack helpers ----------------
__device__ __forceinline__ uint2 pack_h4(float a, float b, float c, float d) {
    __half2 p0 = __floats2half2_rn(a, b);
    __half2 p1 = __floats2half2_rn(c, d);
    uint2 u;
    u.x = *(uint32_t*)&p0;
    u.y = *(uint32_t*)&p1;
    return u;
}

// ---------------- K1: count || (hdelta0 + cvt hbar0) || cvt hbar1 ----------------
#define GE_BLOCKS  ((E_TOT + 255) / 256)           // 5860
#define GEL_BLOCKS ((N_NODES * D / 4 + 255) / 256) // 6250

__global__ void count_cvt_kernel(const int* __restrict__ hd0, const int* __restrict__ sd0,
                                 const int* __restrict__ hd1, const int* __restrict__ sd1,
                                 const float* __restrict__ x, const float* __restrict__ hbar0,
                                 const float* __restrict__ hbar1) {
    int b = blockIdx.x;
    if (b < GE_BLOCKS) {
        int i = b * blockDim.x + threadIdx.x;
        if (i >= E_TOT) return;
        int pair, off;
        const int* p;
        if (i < EH)               { pair = 0; p = hd0; off = i; }
        else if (i < EH + ES)     { pair = 1; p = sd0; off = i - EH; }
        else if (i < 2 * EH + ES) { pair = 2; p = hd1; off = i - EH - ES; }
        else                      { pair = 3; p = sd1; off = i - 2 * EH - ES; }
        atomicAdd(&g_cnt[pair * N_NODES + __ldg(p + off)], 1);
    } else if (b < GE_BLOCKS + GEL_BLOCKS) {
        int i = (b - GE_BLOCKS) * blockDim.x + threadIdx.x;
        if (i >= N_NODES * D / 4) return;
        float4 a = __ldg((const float4*)x + i);
        float4 h = __ldg((const float4*)hbar0 + i);
        ((uint2*)g_Hd16)[i] = pack_h4(a.x - h.x, a.y - h.y, a.z - h.z, a.w - h.w);
        ((uint2*)g_hb0h)[i] = pack_h4(h.x, h.y, h.z, h.w);
    } else {
        int i = (b - GE_BLOCKS - GEL_BLOCKS) * blockDim.x + threadIdx.x;
        if (i >= N_NODES * D / 4) return;
        float4 h = __ldg((const float4*)hbar1 + i);
        ((uint2*)g_hb1h)[i] = pack_h4(h.x, h.y, h.z, h.w);
    }
}

// ---------------- scan (4 blocks, one per pair) ----------------
__global__ void scan_kernel() {
    const int p = blockIdx.x;
    int* cnt = g_cnt + p * N_NODES;
    int* off = g_off + p * (N_NODES + 1);
    int* cur = g_cur + p * N_NODES;
    const int T = 1024;
    const int C = (N_NODES + T - 1) / T;
    __shared__ int part[T];
    int t = threadIdx.x;
    int base = t * C;
    int s = 0;
#pragma unroll 1
    for (int i = 0; i < C; i++) {
        int j = base + i;
        if (j < N_NODES) s += cnt[j];
    }
    part[t] = s;
    __syncthreads();
    for (int d2 = 1; d2 < T; d2 <<= 1) {
        int v = (t >= d2) ? part[t - d2] : 0;
        __syncthreads();
        part[t] += v;
        __syncthreads();
    }
    int run = part[t] - s;
#pragma unroll 1
    for (int i = 0; i < C; i++) {
        int j = base + i;
        if (j < N_NODES) {
            off[j] = run;
            cur[j] = run;
            run += cnt[j];
        }
    }
    if (t == T - 1) off[N_NODES] = part[t];
}

__global__ void bucket_all_kernel(const int* __restrict__ hs0, const int* __restrict__ hd0,
                                  const int* __restrict__ ss0, const int* __restrict__ sd0,
                                  const int* __restrict__ hs1, const int* __restrict__ hd1,
                                  const int* __restrict__ ss1, const int* __restrict__ sd1) {
    int i = blockIdx.x * blockDim.x + threadIdx.x;
    if (i >= E_TOT) return;
    int pair, off;
    const int *ps, *pd;
    if (i < EH)               { pair = 0; ps = hs0; pd = hd0; off = i; }
    else if (i < EH + ES)     { pair = 1; ps = ss0; pd = sd0; off = i - EH; }
    else if (i < 2 * EH + ES) { pair = 2; ps = hs1; pd = hd1; off = i - EH - ES; }
    else                      { pair = 3; ps = ss1; pd = sd1; off = i - 2 * EH - ES; }
    int d = __ldg(pd + off);
    int pos = atomicAdd(&g_cur[pair * N_NODES + d], 1);
    g_eidx[eidx_base(pair) + pos] = __ldg(ps + off);
}

// ---------------- fp16 gather primitives (warp-collective, MLP=4) ----------------
__device__ __forceinline__ void acc_add16(float4& a, uint2 u) {
    __half2 h0 = *(__half2*)&u.x;
    __half2 h1 = *(__half2*)&u.y;
    float2 f0 = __half22float2(h0);
    float2 f1 = __half22float2(h1);
    a.x += f0.x; a.y += f0.y; a.z += f1.x; a.w += f1.y;
}
__device__ __forceinline__ void acc_add(float4& a, float4 v) {
    a.x += v.x; a.y += v.y; a.z += v.z; a.w += v.w;
}

__device__ __forceinline__ float4 gather_mean16(const __half* __restrict__ feat,
                                                const int* __restrict__ idx,
                                                int e0, int e1, int lane) {
    float4 a0 = make_float4(0,0,0,0), a1 = a0, a2 = a0, a3 = a0;
    int e = e0;
    for (; e + 4 <= e1; e += 4) {
        int i0 = __ldg(idx + e + 0), i1 = __ldg(idx + e + 1);
        int i2 = __ldg(idx + e + 2), i3 = __ldg(idx + e + 3);
        uint2 u0 = __ldg((const uint2*)(feat + (size_t)i0 * D) + lane);
        uint2 u1 = __ldg((const uint2*)(feat + (size_t)i1 * D) + lane);
        uint2 u2 = __ldg((const uint2*)(feat + (size_t)i2 * D) + lane);
        uint2 u3 = __ldg((const uint2*)(feat + (size_t)i3 * D) + lane);
        acc_add16(a0, u0); acc_add16(a1, u1); acc_add16(a2, u2); acc_add16(a3, u3);
    }
    for (; e < e1; e++) {
        int s = __ldg(idx + e);
        acc_add16(a0, __ldg((const uint2*)(feat + (size_t)s * D) + lane));
    }
    acc_add(a0, a1); acc_add(a2, a3); acc_add(a0, a2);
    float inv = 1.f / fmaxf((float)(e1 - e0), 1.f);
    return make_float4(a0.x * inv, a0.y * inv, a0.z * inv, a0.w * inv);
}

// ---------------- K4: agg0 (pairs 0,1 -> g_neigh0)  ||  agg1_hist (pair 2 -> g_neigh1) ----
#define GAGG_BLOCKS ((N_NODES * 32 + 255) / 256)   // 6250

__global__ void agg_combined_kernel() {
    int b = blockIdx.x;
    if (b < GAGG_BLOCKS) {
        int g = b * blockDim.x + threadIdx.x;
        int w = g >> 5, lane = g & 31;
        if (w >= N_NODES) return;
        const int* offH = g_off + 0 * (N_NODES + 1);
        const int* offD = g_off + 1 * (N_NODES + 1);
        int h0 = __ldg(offH + w), h1 = __ldg(offH + w + 1);
        int d0 = __ldg(offD + w), d1 = __ldg(offD + w + 1);
        float4 o  = gather_mean16(g_hb0h, g_eidx + eidx_base(0), h0, h1, lane);
        float4 dm = gather_mean16(g_Hd16, g_eidx + eidx_base(1), d0, d1, lane);
        o.x += dm.x; o.y += dm.y; o.z += dm.z; o.w += dm.w;
        *(float4*)(g_neigh0 + (size_t)w * D + lane * 4) = o;
    } else {
        int g = (b - GAGG_BLOCKS) * blockDim.x + threadIdx.x;
        int w = g >> 5, lane = g & 31;
        if (w >= N_NODES) return;
        const int* offH = g_off + 2 * (N_NODES + 1);
        int h0 = __ldg(offH + w), h1 = __ldg(offH + w + 1);
        float4 o = gather_mean16(g_hb1h, g_eidx + eidx_base(2), h0, h1, lane);
        *(float4*)(g_neigh1 + (size_t)w * D + lane * 4) = o;
    }
}

// ---------------- agg1_delta: g_neigh1 += mean over pair 3 of g_Hd16 ----------------
__global__ void agg1_delta_kernel() {
    int g = blockIdx.x * blockDim.x + threadIdx.x;
    int w = g >> 5, lane = g & 31;
    if (w >= N_NODES) return;
    const int* offD = g_off + 3 * (N_NODES + 1);
    int d0 = __ldg(offD + w), d1 = __ldg(offD + w + 1);
    if (d0 == d1) return;
    float4 dm = gather_mean16(g_Hd16, g_eidx + eidx_base(3), d0, d1, lane);
    float4* dst = (float4*)(g_neigh1 + (size_t)w * D + lane * 4);
    float4 o = *dst;
    o.x += dm.x; o.y += dm.y; o.z += dm.z; o.w += dm.w;
    *dst = o;
}

// ---------------- HMMA helpers ----------------
__device__ __forceinline__ uint32_t smem_u32(const void* p) {
    uint32_t a;
    asm("{ .reg .u64 t; cvta.to.shared.u64 t, %1; cvt.u32.u64 %0, t; }" : "=r"(a) : "l"(p));
    return a;
}
__device__ __forceinline__ void ldmatrix_x4(uint32_t& r0, uint32_t& r1,
                                            uint32_t& r2, uint32_t& r3, uint32_t addr) {
    asm volatile("ldmatrix.sync.aligned.m8n8.x4.shared.b16 {%0,%1,%2,%3}, [%4];"
                 : "=r"(r0), "=r"(r1), "=r"(r2), "=r"(r3) : "r"(addr));
}
__device__ __forceinline__ void mma_16816(float* c, const uint32_t* a, const uint32_t* b) {
    asm volatile("mma.sync.aligned.m16n8k16.row.col.f32.f16.f16.f32 "
                 "{%0,%1,%2,%3}, {%4,%5,%6,%7}, {%8,%9}, {%0,%1,%2,%3};"
                 : "+f"(c[0]), "+f"(c[1]), "+f"(c[2]), "+f"(c[3])
                 : "r"(a[0]), "r"(a[1]), "r"(a[2]), "r"(a[3]), "r"(b[0]), "r"(b[1]));
}

// ---------------- HMMA GEMM + bias + ReLU (fp16 operands, fp32 accum) ----------------
// Tiles: As[BM][BK+8] fp16 (row-major, k contiguous), Bs[BN][BK+8] fp16 (= W rows).
// Warp grid WARPS_M x WARPS_N over BM x BN; warp tile WM x WN (WM/16 x WN/8 frags).
// Double-buffered smem, 1 __syncthreads per k-iter. NTILES splits N across blocks.
template <int LAYER, int DOUT, int BM, int BN, int WARPS_M, int WARPS_N,
          int NTILES, int MAXB>
__global__ void __launch_bounds__(256, MAXB)
gemm_hmma_kernel(const float* __restrict__ Hext,
                 const float* __restrict__ W,
                 const float* __restrict__ bias,
                 const float* __restrict__ hbar1,   // layer0 only
                 float* __restrict__ outext) {
    constexpr int BK = 32, K = 2 * D, NK = K / BK;
    constexpr int WM = BM / WARPS_M;       // 32
    constexpr int WN = BN / WARPS_N;       // 32 or 16
    constexpr int MI = WM / 16;            // 2
    constexpr int NJ = WN / 8;             // 4 or 2
    constexpr int PITCH = BK + 8;          // 40 halves = 80 B (16B-aligned rows)
    constexpr int ASTRIDE = BM * PITCH;    // halves per A buffer
    constexpr int BSTRIDE = BN * PITCH;
    constexpr int NA = (BM * BK) / (256 * 4);   // float4 loads per thread
    constexpr int NB = (BN * BK) / (256 * 4);

    const float* H     = (LAYER == 0) ? Hext     : g_H1;
    const float* neigh = (LAYER == 0) ? g_neigh0 : g_neigh1;
    float* out         = (LAYER == 0) ? g_H1     : outext;

    extern __shared__ __half smemh[];
    __half* AsBase = smemh;                    // [2][BM][PITCH]
    __half* BsBase = smemh + 2 * ASTRIDE;      // [2][BN][PITCH]

    const int t      = threadIdx.x;
    const int lane   = t & 31;
    const int warp   = t >> 5;
    const int warp_m = warp % WARPS_M;
    const int warp_n = warp / WARPS_M;
    const int tile   = (NTILES == 1) ? blockIdx.x : (blockIdx.x / NTILES);
    const int nb0    = (NTILES == 1) ? 0 : (blockIdx.x % NTILES) * BN;
    const int row0   = tile * BM;

    float4 pa[NA], pb[NB];

    auto load_tile = [&](int kit) {
        const int k0 = kit * BK;
        const float* Asrc = (k0 < D) ? (H + k0) : (neigh + (k0 - D));
#pragma unroll
        for (int v = 0; v < NA; v++) {
            int id = v * 256 + t;
            int m  = id >> 3;
            int kq = id & 7;
            int r  = min(row0 + m, N_NODES - 1);
            pa[v] = __ldg((const float4*)(Asrc + (size_t)r * D) + kq);
        }
#pragma unroll
        for (int v = 0; v < NB; v++) {
            int id = v * 256 + t;
            int n  = nb0 + (id >> 3);
            int kq = id & 7;
            pb[v] = (n < DOUT) ? __ldg((const float4*)(W + (size_t)n * K + k0) + kq)
                               : make_float4(0.f, 0.f, 0.f, 0.f);
        }
    };
    auto store_tile = [&](int buf) {
        __half* As = AsBase + buf * ASTRIDE;
        __half* Bs = BsBase + buf * BSTRIDE;
#pragma unroll
        for (int v = 0; v < NA; v++) {
            int id = v * 256 + t;
            int m  = id >> 3;
            int kq = id & 7;
            *(uint2*)(As + m * PITCH + kq * 4) = pack_h4(pa[v].x, pa[v].y, pa[v].z, pa[v].w);
        }
#pragma unroll
        for (int v = 0; v < NB; v++) {
            int id = v * 256 + t;
            int n  = id >> 3;
            int kq = id & 7;
            *(uint2*)(Bs + n * PITCH + kq * 4) = pack_h4(pb[v].x, pb[v].y, pb[v].z, pb[v].w);
        }
    };

    float acc[MI][NJ][4];
#pragma unroll
    for (int i = 0; i < MI; i++)
#pragma unroll
        for (int j = 0; j < NJ; j++)
#pragma unroll
            for (int q = 0; q < 4; q++) acc[i][j][q] = 0.f;

    load_tile(0);
    store_tile(0);
    load_tile(1);
    __syncthreads();

    for (int kit = 0; kit < NK; kit++) {
        if (kit + 1 < NK) store_tile((kit + 1) & 1);
        if (kit + 2 < NK) load_tile(kit + 2);

        const __half* As = AsBase + (kit & 1) * ASTRIDE;
        const __half* Bs = BsBase + (kit & 1) * BSTRIDE;
        const uint32_t asb = smem_u32(As);
        const uint32_t bsb = smem_u32(Bs);

#pragma unroll
        for (int ks = 0; ks < BK / 16; ks++) {
            // A fragments: MI tiles of m16k16
            uint32_t afr[MI][4];
#pragma unroll
            for (int mi = 0; mi < MI; mi++) {
                int m = warp_m * WM + mi * 16 + (lane & 15);
                uint32_t addr = asb + (m * PITCH + ks * 16 + (lane >> 4) * 8) * 2;
                ldmatrix_x4(afr[mi][0], afr[mi][1], afr[mi][2], afr[mi][3], addr);
            }
            // B fragments: NJ/2 x4-loads, each covers 2 n8 tiles
            uint32_t bfr[NJ][2];
#pragma unroll
            for (int nj2 = 0; nj2 < NJ / 2; nj2++) {
                int n = warp_n * WN + nj2 * 16 + (lane & 7) + ((lane >> 4) << 3);
                uint32_t addr = bsb + (n * PITCH + ks * 16 + ((lane >> 3) & 1) * 8) * 2;
                uint32_t r0, r1, r2, r3;
                ldmatrix_x4(r0, r1, r2, r3, addr);
                bfr[2 * nj2 + 0][0] = r0; bfr[2 * nj2 + 0][1] = r1;
                bfr[2 * nj2 + 1][0] = r2; bfr[2 * nj2 + 1][1] = r3;
            }
#pragma unroll
            for (int mi = 0; mi < MI; mi++)
#pragma unroll
                for (int nj = 0; nj < NJ; nj++)
                    mma_16816(acc[mi][nj], afr[mi], bfr[nj]);
        }
        __syncthreads();
    }

    // ---- epilogue: fragment layout: d0,d1 -> (row lane/4, cols 2*(lane%4)+{0,1});
    //                                 d2,d3 -> (row lane/4 + 8, same cols)
#pragma unroll
    for (int mi = 0; mi < MI; mi++) {
#pragma unroll
        for (int nj = 0; nj < NJ; nj++) {
            int c  = nb0 + warp_n * WN + nj * 8 + 2 * (lane & 3);
            int r0 = row0 + warp_m * WM + mi * 16 + (lane >> 2);
            int r1 = r0 + 8;
            float b0 = (c     < DOUT) ? __ldg(bias + c)     : 0.f;
            float b1 = (c + 1 < DOUT) ? __ldg(bias + c + 1) : 0.f;
            float v00 = fmaxf(acc[mi][nj][0] + b0, 0.f);
            float v01 = fmaxf(acc[mi][nj][1] + b1, 0.f);
            float v10 = fmaxf(acc[mi][nj][2] + b0, 0.f);
            float v11 = fmaxf(acc[mi][nj][3] + b1, 0.f);
            if (LAYER == 0) {
                if (r0 < N_NODES) {
                    *(float2*)(out + (size_t)r0 * DOUT + c) = make_float2(v00, v01);
                    float2 hb = *(const float2*)(hbar1 + (size_t)r0 * D + c);
                    __half2 hd = __floats2half2_rn(v00 - hb.x, v01 - hb.y);
                    *(__half2*)(g_Hd16 + (size_t)r0 * D + c) = hd;
                }
                if (r1 < N_NODES) {
                    *(float2*)(out + (size_t)r1 * DOUT + c) = make_float2(v10, v11);
                    float2 hb = *(const float2*)(hbar1 + (size_t)r1 * D + c);
                    __half2 hd = __floats2half2_rn(v10 - hb.x, v11 - hb.y);
                    *(__half2*)(g_Hd16 + (size_t)r1 * D + c) = hd;
                }
            } else {
                if (r0 < N_NODES) {
                    if (c     < DOUT) out[(size_t)r0 * DOUT + c]     = v00;
                    if (c + 1 < DOUT) out[(size_t)r0 * DOUT + c + 1] = v01;
                }
                if (r1 < N_NODES) {
                    if (c     < DOUT) out[(size_t)r1 * DOUT + c]     = v10;
                    if (c + 1 < DOUT) out[(size_t)r1 * DOUT + c + 1] = v11;
                }
            }
        }
    }
}

// ---------------- launch ----------------
extern "C" void kernel_launch(void* const* d_in, const int* in_sizes, int n_in,
                              void* d_out, int out_size) {
    const float* x     = (const float*)d_in[0];
    const float* hbar0 = (const float*)d_in[1];
    const float* hbar1 = (const float*)d_in[2];
    const float* W0    = (const float*)d_in[3];
    const float* b0    = (const float*)d_in[4];
    const float* W1    = (const float*)d_in[5];
    const float* b1    = (const float*)d_in[6];
    const int* hsrc0   = (const int*)d_in[7];
    const int* hdst0   = (const int*)d_in[8];
    const int* ssrc0   = (const int*)d_in[9];
    const int* sdst0   = (const int*)d_in[10];
    const int* hsrc1   = (const int*)d_in[11];
    const int* hdst1   = (const int*)d_in[12];
    const int* ssrc1   = (const int*)d_in[13];
    const int* sdst1   = (const int*)d_in[14];
    float* out = (float*)d_out;

    // dynamic smem: 2 buffers * (BM+BN) * (BK+8) halves * 2B
    const int SM0 = 2 * (128 + 64) * 40 * 2;   // 30720 B
    const int SM1 = 2 * (64 + 64) * 40 * 2;    // 20480 B
    cudaFuncSetAttribute((const void*)gemm_hmma_kernel<0, 128, 128, 64, 4, 2, 2, 2>,
                         cudaFuncAttributeMaxDynamicSharedMemorySize, SM0);
    cudaFuncSetAttribute((const void*)gemm_hmma_kernel<1, NCLS, 64, 64, 2, 4, 1, 3>,
                         cudaFuncAttributeMaxDynamicSharedMemorySize, SM1);

    // ---- K0: zero counters ----
    void* cnt_ptr = nullptr;
    cudaGetSymbolAddress(&cnt_ptr, g_cnt);
    cudaMemsetAsync(cnt_ptr, 0, sizeof(int) * 4 * N_NODES);

    // ---- K1: count || (hdelta0+cvt hbar0) || cvt hbar1 ----
    count_cvt_kernel<<<GE_BLOCKS + 2 * GEL_BLOCKS, 256>>>(hdst0, sdst0, hdst1, sdst1,
                                                          x, hbar0, hbar1);

    // ---- K2/K3: scan + bucket ----
    scan_kernel<<<4, 1024>>>();
    bucket_all_kernel<<<GE_BLOCKS, 256>>>(hsrc0, hdst0, ssrc0, sdst0,
                                          hsrc1, hdst1, ssrc1, sdst1);

    // ---- K4: agg0 || agg1_hist (fp16 gathers) ----
    agg_combined_kernel<<<2 * GAGG_BLOCKS, 256>>>();

    // ---- K5: gemm0 HMMA, BM=128 x BN=64, N split in 2 (grid 782), fused fp16 hdelta1 ----
    gemm_hmma_kernel<0, 128, 128, 64, 4, 2, 2, 2>
        <<<((N_NODES + 127) / 128) * 2, 256, SM0>>>(x, W0, b0, hbar1, nullptr);

    // ---- K6: agg1_delta (fp16 gather) ----
    agg1_delta_kernel<<<GAGG_BLOCKS, 256>>>();

    // ---- K7: gemm1 HMMA, BM=64 x BN=64 (grid 782) ----
    gemm_hmma_kernel<1, NCLS, 64, 64, 2, 4, 1, 3>
        <<<(N_NODES + 63) / 64, 256, SM1>>>(nullptr, W1, b1, nullptr, out);
}